// round 2
// baseline (speedup 1.0000x reference)
#include <cuda_runtime.h>
#include <cstdint>

#define NA 100000
#define NH 20000
#define NE 1000000
#define EL 200000
#define D  128

// ---------------- device scratch (static, no allocations) ----------------
__device__ int   g_cnt_a[NA];
__device__ int   g_cnt_h[NH];
__device__ int   g_ptr_a[NA + 1];
__device__ int   g_ptr_h[NH + 1];
__device__ int   g_cur_a[NA];
__device__ int   g_cur_h[NH];
__device__ int   g_csr_ah[NE];   // edges grouped by hotel dst, storing author src
__device__ int   g_csr_ha[NE];   // edges grouped by author dst, storing hotel src
__device__ float g_agg_a[(size_t)NA * D];
__device__ float g_agg_h[(size_t)NH * D];
__device__ float g_h_a[(size_t)NA * D];
__device__ float g_h_h[(size_t)NH * D];
__device__ float g_z_a[(size_t)NA * D];
__device__ float g_z_h[(size_t)NH * D];

// ---------------- small utility kernels ----------------
__global__ void zero_int_kernel(int* p, int n) {
    int i = blockIdx.x * blockDim.x + threadIdx.x;
    if (i < n) p[i] = 0;
}

__global__ void copy_int_kernel(int* dst, const int* src, int n) {
    int i = blockIdx.x * blockDim.x + threadIdx.x;
    if (i < n) dst[i] = src[i];
}

__global__ void hist_kernel(const int* __restrict__ dst, int* __restrict__ cnt, int n) {
    int i = blockIdx.x * blockDim.x + threadIdx.x;
    if (i < n) atomicAdd(&cnt[dst[i]], 1);
}

__global__ void scatter_kernel(const int* __restrict__ src, const int* __restrict__ dst,
                               int* __restrict__ cur, int* __restrict__ csr, int n) {
    int i = blockIdx.x * blockDim.x + threadIdx.x;
    if (i < n) {
        int d = dst[i];
        int p = atomicAdd(&cur[d], 1);
        csr[p] = src[i];
    }
}

// single-block exclusive scan (n up to ~100k), also writes ptr[n] = total
__global__ void exscan_kernel(const int* __restrict__ cnt, int* __restrict__ ptr, int n) {
    __shared__ int warp_sums[32];
    __shared__ int s_carry;
    int tid = threadIdx.x;
    int lane = tid & 31, wid = tid >> 5;
    if (tid == 0) s_carry = 0;
    __syncthreads();
    for (int base = 0; base < n; base += 1024) {
        int i = base + tid;
        int v = (i < n) ? cnt[i] : 0;
        int x = v;
        #pragma unroll
        for (int o = 1; o < 32; o <<= 1) {
            int y = __shfl_up_sync(0xFFFFFFFFu, x, o);
            if (lane >= o) x += y;
        }
        if (lane == 31) warp_sums[wid] = x;
        __syncthreads();
        if (wid == 0) {
            int s = warp_sums[lane];
            #pragma unroll
            for (int o = 1; o < 32; o <<= 1) {
                int y = __shfl_up_sync(0xFFFFFFFFu, s, o);
                if (lane >= o) s += y;
            }
            warp_sums[lane] = s;
        }
        __syncthreads();
        int incl = x + ((wid > 0) ? warp_sums[wid - 1] : 0);
        int carry = s_carry;
        if (i < n) ptr[i] = carry + incl - v;
        __syncthreads();
        if (tid == 1023) s_carry = carry + incl;
        __syncthreads();
    }
    if (tid == 0) ptr[n] = s_carry;
}

// ---------------- mean aggregation: one warp per destination node ----------------
__global__ void agg_mean_kernel(const float* __restrict__ X,
                                const int* __restrict__ ptr,
                                const int* __restrict__ idx,
                                float* __restrict__ out, int n) {
    int w = (blockIdx.x * blockDim.x + threadIdx.x) >> 5;
    int lane = threadIdx.x & 31;
    if (w >= n) return;
    int s = ptr[w], e = ptr[w + 1];
    float ax = 0.f, ay = 0.f, az = 0.f, aw = 0.f;
    int i = s;
    for (; i + 2 <= e; i += 2) {
        int s0 = __ldg(&idx[i]);
        int s1 = __ldg(&idx[i + 1]);
        float4 v0 = *reinterpret_cast<const float4*>(X + (size_t)s0 * D + lane * 4);
        float4 v1 = *reinterpret_cast<const float4*>(X + (size_t)s1 * D + lane * 4);
        ax += v0.x; ay += v0.y; az += v0.z; aw += v0.w;
        ax += v1.x; ay += v1.y; az += v1.z; aw += v1.w;
    }
    if (i < e) {
        int s0 = __ldg(&idx[i]);
        float4 v0 = *reinterpret_cast<const float4*>(X + (size_t)s0 * D + lane * 4);
        ax += v0.x; ay += v0.y; az += v0.z; aw += v0.w;
    }
    int deg = e - s;
    float inv = 1.0f / (float)(deg > 0 ? deg : 1);
    float4 r = make_float4(ax * inv, ay * inv, az * inv, aw * inv);
    *reinterpret_cast<float4*>(out + (size_t)w * D + lane * 4) = r;
}

// ---------------- fused GEMM: C = op(A0@W0 + A1@W1 + bias), K=256 (128+128) ----------------
// BM=64, BN=128, BK=32, 256 threads, TM=4 x TN=8 per thread
__global__ void __launch_bounds__(256)
gemm256_kernel(const float* __restrict__ A0, int lda0,
               const float* __restrict__ A1, int lda1,
               const float* __restrict__ W0, const float* __restrict__ W1,
               const float* __restrict__ bias,
               float* __restrict__ C, int ldc, int M, int relu) {
    __shared__ float As[64][36];    // BK=32 + pad 4
    __shared__ float Ws[32][132];   // BN=128 + pad 4

    int tid = threadIdx.x;
    int tx = tid & 15;       // col group: cols tx*8 .. tx*8+7
    int ty = tid >> 4;       // row group: rows ty*4 .. ty*4+3
    int row0 = blockIdx.x * 64;

    float acc[4][8];
    #pragma unroll
    for (int r = 0; r < 4; r++)
        #pragma unroll
        for (int c = 0; c < 8; c++) acc[r][c] = 0.f;

    #pragma unroll 1
    for (int kc = 0; kc < 8; ++kc) {
        const float* A = (kc < 4) ? A0 : A1;
        int lda        = (kc < 4) ? lda0 : lda1;
        const float* W = (kc < 4) ? W0 : W1;
        int koff = (kc & 3) * 32;

        // A tile: 64 rows x 32 k = 512 float4, 2 per thread
        #pragma unroll
        for (int i = 0; i < 2; i++) {
            int p = tid + i * 256;
            int r = p >> 3;
            int k4 = (p & 7) * 4;
            int gr = row0 + r;
            float4 v = make_float4(0.f, 0.f, 0.f, 0.f);
            if (gr < M)
                v = *reinterpret_cast<const float4*>(A + (size_t)gr * lda + koff + k4);
            *reinterpret_cast<float4*>(&As[r][k4]) = v;
        }
        // W tile: 32 k x 128 n = 1024 float4, 4 per thread
        #pragma unroll
        for (int i = 0; i < 4; i++) {
            int p = tid + i * 256;
            int kk = p >> 5;
            int c4 = (p & 31) * 4;
            float4 v = *reinterpret_cast<const float4*>(W + (size_t)(koff + kk) * 128 + c4);
            *reinterpret_cast<float4*>(&Ws[kk][c4]) = v;
        }
        __syncthreads();

        #pragma unroll
        for (int kk = 0; kk < 32; kk++) {
            float a[4];
            #pragma unroll
            for (int r = 0; r < 4; r++) a[r] = As[ty * 4 + r][kk];
            float4 w0 = *reinterpret_cast<const float4*>(&Ws[kk][tx * 8]);
            float4 w1 = *reinterpret_cast<const float4*>(&Ws[kk][tx * 8 + 4]);
            float w[8] = {w0.x, w0.y, w0.z, w0.w, w1.x, w1.y, w1.z, w1.w};
            #pragma unroll
            for (int r = 0; r < 4; r++)
                #pragma unroll
                for (int c = 0; c < 8; c++)
                    acc[r][c] += a[r] * w[c];
        }
        __syncthreads();
    }

    float b[8];
    {
        float4 b0 = *reinterpret_cast<const float4*>(bias + tx * 8);
        float4 b1 = *reinterpret_cast<const float4*>(bias + tx * 8 + 4);
        b[0] = b0.x; b[1] = b0.y; b[2] = b0.z; b[3] = b0.w;
        b[4] = b1.x; b[5] = b1.y; b[6] = b1.z; b[7] = b1.w;
    }
    #pragma unroll
    for (int r = 0; r < 4; r++) {
        int gr = row0 + ty * 4 + r;
        if (gr >= M) continue;
        float o[8];
        #pragma unroll
        for (int c = 0; c < 8; c++) {
            float v = acc[r][c] + b[c];
            if (relu) v = fmaxf(v, 0.f);
            o[c] = v;
        }
        float* cp = C + (size_t)gr * ldc + tx * 8;
        *reinterpret_cast<float4*>(cp)     = make_float4(o[0], o[1], o[2], o[3]);
        *reinterpret_cast<float4*>(cp + 4) = make_float4(o[4], o[5], o[6], o[7]);
    }
}

// ---------------- decoder: gather z1 rows (one warp per link edge) ----------------
__global__ void gather_z1_kernel(const float* __restrict__ za, const float* __restrict__ zh,
                                 const int* __restrict__ row, const int* __restrict__ col,
                                 float* __restrict__ z1, int n) {
    int w = (blockIdx.x * blockDim.x + threadIdx.x) >> 5;
    int lane = threadIdx.x & 31;
    if (w >= n) return;
    int r = __ldg(&row[w]);
    int c = __ldg(&col[w]);
    float4 a = *reinterpret_cast<const float4*>(za + (size_t)r * D + lane * 4);
    float4 b = *reinterpret_cast<const float4*>(zh + (size_t)c * D + lane * 4);
    *reinterpret_cast<float4*>(z1 + (size_t)w * 256 + lane * 4)       = a;
    *reinterpret_cast<float4*>(z1 + (size_t)w * 256 + 128 + lane * 4) = b;
}

// ---------------- pred = z2 @ W_lin2 + b_lin2 (one warp per row) ----------------
__global__ void pred_kernel(const float* __restrict__ z2, const float* __restrict__ w2,
                            const float* __restrict__ b2, float* __restrict__ out, int n) {
    int w = (blockIdx.x * blockDim.x + threadIdx.x) >> 5;
    int lane = threadIdx.x & 31;
    if (w >= n) return;
    float4 v  = *reinterpret_cast<const float4*>(z2 + (size_t)w * D + lane * 4);
    float4 ww = *reinterpret_cast<const float4*>(w2 + lane * 4);
    float s = v.x * ww.x + v.y * ww.y + v.z * ww.z + v.w * ww.w;
    #pragma unroll
    for (int o = 16; o > 0; o >>= 1) s += __shfl_xor_sync(0xFFFFFFFFu, s, o);
    if (lane == 0) out[w] = s + b2[0];
}

// ---------------- host launch ----------------
static inline int divup(int a, int b) { return (a + b - 1) / b; }

extern "C" void kernel_launch(void* const* d_in, const int* in_sizes, int n_in,
                              void* d_out, int out_size) {
    const float* x_a    = (const float*)d_in[0];
    const float* x_h    = (const float*)d_in[1];
    const int*   ah_src = (const int*)d_in[2];
    const int*   ah_dst = (const int*)d_in[3];
    const int*   ha_src = (const int*)d_in[4];
    const int*   ha_dst = (const int*)d_in[5];
    const int*   e_row  = (const int*)d_in[6];
    const int*   e_col  = (const int*)d_in[7];

    // Detect input ordering: signature order has bias (128) at index 9,
    // dict order has W1_ah_r (16384) at index 9.
    bool sig = (in_sizes[9] == 128);
    const float *W1_ah_l, *W1_ah_r, *W1_ha_l, *W1_ha_r;
    const float *W2_ah_l, *W2_ah_r, *W2_ha_l, *W2_ha_r;
    const float *b1_ah, *b1_ha, *b2_ah, *b2_ha;
    if (sig) {
        W1_ah_l = (const float*)d_in[8];  b1_ah = (const float*)d_in[9];
        W1_ah_r = (const float*)d_in[10];
        W1_ha_l = (const float*)d_in[11]; b1_ha = (const float*)d_in[12];
        W1_ha_r = (const float*)d_in[13];
        W2_ah_l = (const float*)d_in[14]; b2_ah = (const float*)d_in[15];
        W2_ah_r = (const float*)d_in[16];
        W2_ha_l = (const float*)d_in[17]; b2_ha = (const float*)d_in[18];
        W2_ha_r = (const float*)d_in[19];
    } else {
        W1_ah_l = (const float*)d_in[8];  W1_ah_r = (const float*)d_in[9];
        W1_ha_l = (const float*)d_in[10]; W1_ha_r = (const float*)d_in[11];
        W2_ah_l = (const float*)d_in[12]; W2_ah_r = (const float*)d_in[13];
        W2_ha_l = (const float*)d_in[14]; W2_ha_r = (const float*)d_in[15];
        b1_ah = (const float*)d_in[16];   b1_ha = (const float*)d_in[17];
        b2_ah = (const float*)d_in[18];   b2_ha = (const float*)d_in[19];
    }
    const float* W_lin1 = (const float*)d_in[20];
    const float* b_lin1 = (const float*)d_in[21];
    const float* W_lin2 = (const float*)d_in[22];
    const float* b_lin2 = (const float*)d_in[23];

    float* out  = (float*)d_out;
    float* pred = out;
    float* z1   = out + EL;
    float* z2   = out + EL + (size_t)EL * 256;

    // resolve scratch symbols
    int *cnt_a, *cnt_h, *ptr_a, *ptr_h, *cur_a, *cur_h, *csr_ah, *csr_ha;
    float *agg_a, *agg_h, *h_a, *h_h, *z_a, *z_h;
    cudaGetSymbolAddress((void**)&cnt_a, g_cnt_a);
    cudaGetSymbolAddress((void**)&cnt_h, g_cnt_h);
    cudaGetSymbolAddress((void**)&ptr_a, g_ptr_a);
    cudaGetSymbolAddress((void**)&ptr_h, g_ptr_h);
    cudaGetSymbolAddress((void**)&cur_a, g_cur_a);
    cudaGetSymbolAddress((void**)&cur_h, g_cur_h);
    cudaGetSymbolAddress((void**)&csr_ah, g_csr_ah);
    cudaGetSymbolAddress((void**)&csr_ha, g_csr_ha);
    cudaGetSymbolAddress((void**)&agg_a, g_agg_a);
    cudaGetSymbolAddress((void**)&agg_h, g_agg_h);
    cudaGetSymbolAddress((void**)&h_a, g_h_a);
    cudaGetSymbolAddress((void**)&h_h, g_h_h);
    cudaGetSymbolAddress((void**)&z_a, g_z_a);
    cudaGetSymbolAddress((void**)&z_h, g_z_h);

    const int TB = 256;

    // ---- CSR build: a->h edges grouped by hotel dst ----
    zero_int_kernel<<<divup(NH, TB), TB>>>(cnt_h, NH);
    hist_kernel<<<divup(NE, TB), TB>>>(ah_dst, cnt_h, NE);
    exscan_kernel<<<1, 1024>>>(cnt_h, ptr_h, NH);
    copy_int_kernel<<<divup(NH, TB), TB>>>(cur_h, ptr_h, NH);
    scatter_kernel<<<divup(NE, TB), TB>>>(ah_src, ah_dst, cur_h, csr_ah, NE);

    // ---- CSR build: h->a edges grouped by author dst ----
    zero_int_kernel<<<divup(NA, TB), TB>>>(cnt_a, NA);
    hist_kernel<<<divup(NE, TB), TB>>>(ha_dst, cnt_a, NE);
    exscan_kernel<<<1, 1024>>>(cnt_a, ptr_a, NA);
    copy_int_kernel<<<divup(NA, TB), TB>>>(cur_a, ptr_a, NA);
    scatter_kernel<<<divup(NE, TB), TB>>>(ha_src, ha_dst, cur_a, csr_ha, NE);

    // ---- Layer 1 ----
    agg_mean_kernel<<<divup(NH * 32, TB), TB>>>(x_a, ptr_h, csr_ah, agg_h, NH);
    gemm256_kernel<<<divup(NH, 64), TB>>>(agg_h, D, x_h, D, W1_ah_l, W1_ah_r, b1_ah, h_h, D, NH, 1);
    agg_mean_kernel<<<divup(NA * 32, TB), TB>>>(x_h, ptr_a, csr_ha, agg_a, NA);
    gemm256_kernel<<<divup(NA, 64), TB>>>(agg_a, D, x_a, D, W1_ha_l, W1_ha_r, b1_ha, h_a, D, NA, 1);

    // ---- Layer 2 ----
    agg_mean_kernel<<<divup(NH * 32, TB), TB>>>(h_a, ptr_h, csr_ah, agg_h, NH);
    gemm256_kernel<<<divup(NH, 64), TB>>>(agg_h, D, h_h, D, W2_ah_l, W2_ah_r, b2_ah, z_h, D, NH, 0);
    agg_mean_kernel<<<divup(NA * 32, TB), TB>>>(h_h, ptr_a, csr_ha, agg_a, NA);
    gemm256_kernel<<<divup(NA, 64), TB>>>(agg_a, D, h_a, D, W2_ha_l, W2_ha_r, b2_ha, z_a, D, NA, 0);

    // ---- Decoder ----
    gather_z1_kernel<<<divup(EL * 32, TB), TB>>>(z_a, z_h, e_row, e_col, z1, EL);
    gemm256_kernel<<<divup(EL, 64), TB>>>(z1, 256, z1 + 128, 256, W_lin1, W_lin1 + 128 * 128,
                                          b_lin1, z2, D, EL, 1);
    pred_kernel<<<divup(EL * 32, TB), TB>>>(z2, W_lin2, b_lin2, pred, EL);
}

// round 6
// speedup vs baseline: 1.0003x; 1.0003x over previous
#include <cuda_runtime.h>
#include <cstdint>

#define NA 100000
#define NH 20000
#define NE 1000000
#define EL 200000
#define D  128

// ---------------- device scratch (static, no allocations) ----------------
__device__ int   g_cnt_a[NA];
__device__ int   g_cnt_h[NH];
__device__ int   g_ptr_a[NA + 1];
__device__ int   g_ptr_h[NH + 1];
__device__ int   g_cur_a[NA];
__device__ int   g_cur_h[NH];
__device__ int   g_csr_ah[NE];   // edges grouped by hotel dst, storing author src
__device__ int   g_csr_ha[NE];   // edges grouped by author dst, storing hotel src
__device__ float g_agg_a[(size_t)NA * D];
__device__ float g_agg_h[(size_t)NH * D];
__device__ float g_h_a[(size_t)NA * D];
__device__ float g_h_h[(size_t)NH * D];
__device__ float g_z_a[(size_t)NA * D];
__device__ float g_z_h[(size_t)NH * D];

// ---------------- small utility kernels ----------------
__global__ void zero_int_kernel(int* p, int n) {
    int i = blockIdx.x * blockDim.x + threadIdx.x;
    if (i < n) p[i] = 0;
}

__global__ void copy_int_kernel(int* dst, const int* src, int n) {
    int i = blockIdx.x * blockDim.x + threadIdx.x;
    if (i < n) dst[i] = src[i];
}

__global__ void hist_kernel(const int* __restrict__ dst, int* __restrict__ cnt, int n) {
    int i = blockIdx.x * blockDim.x + threadIdx.x;
    if (i < n) atomicAdd(&cnt[dst[i]], 1);
}

__global__ void scatter_kernel(const int* __restrict__ src, const int* __restrict__ dst,
                               int* __restrict__ cur, int* __restrict__ csr, int n) {
    int i = blockIdx.x * blockDim.x + threadIdx.x;
    if (i < n) {
        int d = dst[i];
        int p = atomicAdd(&cur[d], 1);
        csr[p] = src[i];
    }
}

// single-block exclusive scan (n up to ~100k), also writes ptr[n] = total
__global__ void exscan_kernel(const int* __restrict__ cnt, int* __restrict__ ptr, int n) {
    __shared__ int warp_sums[32];
    __shared__ int s_carry;
    int tid = threadIdx.x;
    int lane = tid & 31, wid = tid >> 5;
    if (tid == 0) s_carry = 0;
    __syncthreads();
    for (int base = 0; base < n; base += 1024) {
        int i = base + tid;
        int v = (i < n) ? cnt[i] : 0;
        int x = v;
        #pragma unroll
        for (int o = 1; o < 32; o <<= 1) {
            int y = __shfl_up_sync(0xFFFFFFFFu, x, o);
            if (lane >= o) x += y;
        }
        if (lane == 31) warp_sums[wid] = x;
        __syncthreads();
        if (wid == 0) {
            int s = warp_sums[lane];
            #pragma unroll
            for (int o = 1; o < 32; o <<= 1) {
                int y = __shfl_up_sync(0xFFFFFFFFu, s, o);
                if (lane >= o) s += y;
            }
            warp_sums[lane] = s;
        }
        __syncthreads();
        int incl = x + ((wid > 0) ? warp_sums[wid - 1] : 0);
        int carry = s_carry;
        if (i < n) ptr[i] = carry + incl - v;
        __syncthreads();
        if (tid == 1023) s_carry = carry + incl;
        __syncthreads();
    }
    if (tid == 0) ptr[n] = s_carry;
}

// ---------------- mean aggregation: one warp per destination node ----------------
__global__ void agg_mean_kernel(const float* __restrict__ X,
                                const int* __restrict__ ptr,
                                const int* __restrict__ idx,
                                float* __restrict__ out, int n) {
    int w = (blockIdx.x * blockDim.x + threadIdx.x) >> 5;
    int lane = threadIdx.x & 31;
    if (w >= n) return;
    int s = ptr[w], e = ptr[w + 1];
    float ax = 0.f, ay = 0.f, az = 0.f, aw = 0.f;
    int i = s;
    for (; i + 2 <= e; i += 2) {
        int s0 = __ldg(&idx[i]);
        int s1 = __ldg(&idx[i + 1]);
        float4 v0 = *reinterpret_cast<const float4*>(X + (size_t)s0 * D + lane * 4);
        float4 v1 = *reinterpret_cast<const float4*>(X + (size_t)s1 * D + lane * 4);
        ax += v0.x; ay += v0.y; az += v0.z; aw += v0.w;
        ax += v1.x; ay += v1.y; az += v1.z; aw += v1.w;
    }
    if (i < e) {
        int s0 = __ldg(&idx[i]);
        float4 v0 = *reinterpret_cast<const float4*>(X + (size_t)s0 * D + lane * 4);
        ax += v0.x; ay += v0.y; az += v0.z; aw += v0.w;
    }
    int deg = e - s;
    float inv = 1.0f / (float)(deg > 0 ? deg : 1);
    float4 r = make_float4(ax * inv, ay * inv, az * inv, aw * inv);
    *reinterpret_cast<float4*>(out + (size_t)w * D + lane * 4) = r;
}

// ---------------- fused GEMM: C = op(A0@W0 + A1@W1 + bias), K=256 (128+128) ----------------
// BM=64, BN=128, BK=32, 256 threads, TM=4 x TN=8 per thread
__global__ void __launch_bounds__(256)
gemm256_kernel(const float* __restrict__ A0, int lda0,
               const float* __restrict__ A1, int lda1,
               const float* __restrict__ W0, const float* __restrict__ W1,
               const float* __restrict__ bias,
               float* __restrict__ C, int ldc, int M, int relu) {
    __shared__ float As[64][36];    // BK=32 + pad 4
    __shared__ float Ws[32][132];   // BN=128 + pad 4

    int tid = threadIdx.x;
    int tx = tid & 15;       // col group: cols tx*8 .. tx*8+7
    int ty = tid >> 4;       // row group: rows ty*4 .. ty*4+3
    int row0 = blockIdx.x * 64;

    float acc[4][8];
    #pragma unroll
    for (int r = 0; r < 4; r++)
        #pragma unroll
        for (int c = 0; c < 8; c++) acc[r][c] = 0.f;

    #pragma unroll 1
    for (int kc = 0; kc < 8; ++kc) {
        const float* A = (kc < 4) ? A0 : A1;
        int lda        = (kc < 4) ? lda0 : lda1;
        const float* W = (kc < 4) ? W0 : W1;
        int koff = (kc & 3) * 32;

        // A tile: 64 rows x 32 k = 512 float4, 2 per thread
        #pragma unroll
        for (int i = 0; i < 2; i++) {
            int p = tid + i * 256;
            int r = p >> 3;
            int k4 = (p & 7) * 4;
            int gr = row0 + r;
            float4 v = make_float4(0.f, 0.f, 0.f, 0.f);
            if (gr < M)
                v = *reinterpret_cast<const float4*>(A + (size_t)gr * lda + koff + k4);
            *reinterpret_cast<float4*>(&As[r][k4]) = v;
        }
        // W tile: 32 k x 128 n = 1024 float4, 4 per thread
        #pragma unroll
        for (int i = 0; i < 4; i++) {
            int p = tid + i * 256;
            int kk = p >> 5;
            int c4 = (p & 31) * 4;
            float4 v = *reinterpret_cast<const float4*>(W + (size_t)(koff + kk) * 128 + c4);
            *reinterpret_cast<float4*>(&Ws[kk][c4]) = v;
        }
        __syncthreads();

        #pragma unroll
        for (int kk = 0; kk < 32; kk++) {
            float a[4];
            #pragma unroll
            for (int r = 0; r < 4; r++) a[r] = As[ty * 4 + r][kk];
            float4 w0 = *reinterpret_cast<const float4*>(&Ws[kk][tx * 8]);
            float4 w1 = *reinterpret_cast<const float4*>(&Ws[kk][tx * 8 + 4]);
            float w[8] = {w0.x, w0.y, w0.z, w0.w, w1.x, w1.y, w1.z, w1.w};
            #pragma unroll
            for (int r = 0; r < 4; r++)
                #pragma unroll
                for (int c = 0; c < 8; c++)
                    acc[r][c] += a[r] * w[c];
        }
        __syncthreads();
    }

    float b[8];
    {
        float4 b0 = *reinterpret_cast<const float4*>(bias + tx * 8);
        float4 b1 = *reinterpret_cast<const float4*>(bias + tx * 8 + 4);
        b[0] = b0.x; b[1] = b0.y; b[2] = b0.z; b[3] = b0.w;
        b[4] = b1.x; b[5] = b1.y; b[6] = b1.z; b[7] = b1.w;
    }
    #pragma unroll
    for (int r = 0; r < 4; r++) {
        int gr = row0 + ty * 4 + r;
        if (gr >= M) continue;
        float o[8];
        #pragma unroll
        for (int c = 0; c < 8; c++) {
            float v = acc[r][c] + b[c];
            if (relu) v = fmaxf(v, 0.f);
            o[c] = v;
        }
        float* cp = C + (size_t)gr * ldc + tx * 8;
        *reinterpret_cast<float4*>(cp)     = make_float4(o[0], o[1], o[2], o[3]);
        *reinterpret_cast<float4*>(cp + 4) = make_float4(o[4], o[5], o[6], o[7]);
    }
}

// ---------------- decoder: gather z1 rows (one warp per link edge) ----------------
__global__ void gather_z1_kernel(const float* __restrict__ za, const float* __restrict__ zh,
                                 const int* __restrict__ row, const int* __restrict__ col,
                                 float* __restrict__ z1, int n) {
    int w = (blockIdx.x * blockDim.x + threadIdx.x) >> 5;
    int lane = threadIdx.x & 31;
    if (w >= n) return;
    int r = __ldg(&row[w]);
    int c = __ldg(&col[w]);
    float4 a = *reinterpret_cast<const float4*>(za + (size_t)r * D + lane * 4);
    float4 b = *reinterpret_cast<const float4*>(zh + (size_t)c * D + lane * 4);
    *reinterpret_cast<float4*>(z1 + (size_t)w * 256 + lane * 4)       = a;
    *reinterpret_cast<float4*>(z1 + (size_t)w * 256 + 128 + lane * 4) = b;
}

// ---------------- pred = z2 @ W_lin2 + b_lin2 (one warp per row) ----------------
__global__ void pred_kernel(const float* __restrict__ z2, const float* __restrict__ w2,
                            const float* __restrict__ b2, float* __restrict__ out, int n) {
    int w = (blockIdx.x * blockDim.x + threadIdx.x) >> 5;
    int lane = threadIdx.x & 31;
    if (w >= n) return;
    float4 v  = *reinterpret_cast<const float4*>(z2 + (size_t)w * D + lane * 4);
    float4 ww = *reinterpret_cast<const float4*>(w2 + lane * 4);
    float s = v.x * ww.x + v.y * ww.y + v.z * ww.z + v.w * ww.w;
    #pragma unroll
    for (int o = 16; o > 0; o >>= 1) s += __shfl_xor_sync(0xFFFFFFFFu, s, o);
    if (lane == 0) out[w] = s + b2[0];
}

// ---------------- host launch ----------------
static inline int divup(int a, int b) { return (a + b - 1) / b; }

extern "C" void kernel_launch(void* const* d_in, const int* in_sizes, int n_in,
                              void* d_out, int out_size) {
    const float* x_a    = (const float*)d_in[0];
    const float* x_h    = (const float*)d_in[1];
    const int*   ah_src = (const int*)d_in[2];
    const int*   ah_dst = (const int*)d_in[3];
    const int*   ha_src = (const int*)d_in[4];
    const int*   ha_dst = (const int*)d_in[5];
    const int*   e_row  = (const int*)d_in[6];
    const int*   e_col  = (const int*)d_in[7];

    // Detect input ordering: signature order has bias (128) at index 9,
    // dict order has W1_ah_r (16384) at index 9.
    bool sig = (in_sizes[9] == 128);
    const float *W1_ah_l, *W1_ah_r, *W1_ha_l, *W1_ha_r;
    const float *W2_ah_l, *W2_ah_r, *W2_ha_l, *W2_ha_r;
    const float *b1_ah, *b1_ha, *b2_ah, *b2_ha;
    if (sig) {
        W1_ah_l = (const float*)d_in[8];  b1_ah = (const float*)d_in[9];
        W1_ah_r = (const float*)d_in[10];
        W1_ha_l = (const float*)d_in[11]; b1_ha = (const float*)d_in[12];
        W1_ha_r = (const float*)d_in[13];
        W2_ah_l = (const float*)d_in[14]; b2_ah = (const float*)d_in[15];
        W2_ah_r = (const float*)d_in[16];
        W2_ha_l = (const float*)d_in[17]; b2_ha = (const float*)d_in[18];
        W2_ha_r = (const float*)d_in[19];
    } else {
        W1_ah_l = (const float*)d_in[8];  W1_ah_r = (const float*)d_in[9];
        W1_ha_l = (const float*)d_in[10]; W1_ha_r = (const float*)d_in[11];
        W2_ah_l = (const float*)d_in[12]; W2_ah_r = (const float*)d_in[13];
        W2_ha_l = (const float*)d_in[14]; W2_ha_r = (const float*)d_in[15];
        b1_ah = (const float*)d_in[16];   b1_ha = (const float*)d_in[17];
        b2_ah = (const float*)d_in[18];   b2_ha = (const float*)d_in[19];
    }
    const float* W_lin1 = (const float*)d_in[20];
    const float* b_lin1 = (const float*)d_in[21];
    const float* W_lin2 = (const float*)d_in[22];
    const float* b_lin2 = (const float*)d_in[23];

    float* out  = (float*)d_out;
    float* pred = out;
    float* z1   = out + EL;
    float* z2   = out + EL + (size_t)EL * 256;

    // resolve scratch symbols
    int *cnt_a, *cnt_h, *ptr_a, *ptr_h, *cur_a, *cur_h, *csr_ah, *csr_ha;
    float *agg_a, *agg_h, *h_a, *h_h, *z_a, *z_h;
    cudaGetSymbolAddress((void**)&cnt_a, g_cnt_a);
    cudaGetSymbolAddress((void**)&cnt_h, g_cnt_h);
    cudaGetSymbolAddress((void**)&ptr_a, g_ptr_a);
    cudaGetSymbolAddress((void**)&ptr_h, g_ptr_h);
    cudaGetSymbolAddress((void**)&cur_a, g_cur_a);
    cudaGetSymbolAddress((void**)&cur_h, g_cur_h);
    cudaGetSymbolAddress((void**)&csr_ah, g_csr_ah);
    cudaGetSymbolAddress((void**)&csr_ha, g_csr_ha);
    cudaGetSymbolAddress((void**)&agg_a, g_agg_a);
    cudaGetSymbolAddress((void**)&agg_h, g_agg_h);
    cudaGetSymbolAddress((void**)&h_a, g_h_a);
    cudaGetSymbolAddress((void**)&h_h, g_h_h);
    cudaGetSymbolAddress((void**)&z_a, g_z_a);
    cudaGetSymbolAddress((void**)&z_h, g_z_h);

    const int TB = 256;

    // ---- CSR build: a->h edges grouped by hotel dst ----
    zero_int_kernel<<<divup(NH, TB), TB>>>(cnt_h, NH);
    hist_kernel<<<divup(NE, TB), TB>>>(ah_dst, cnt_h, NE);
    exscan_kernel<<<1, 1024>>>(cnt_h, ptr_h, NH);
    copy_int_kernel<<<divup(NH, TB), TB>>>(cur_h, ptr_h, NH);
    scatter_kernel<<<divup(NE, TB), TB>>>(ah_src, ah_dst, cur_h, csr_ah, NE);

    // ---- CSR build: h->a edges grouped by author dst ----
    zero_int_kernel<<<divup(NA, TB), TB>>>(cnt_a, NA);
    hist_kernel<<<divup(NE, TB), TB>>>(ha_dst, cnt_a, NE);
    exscan_kernel<<<1, 1024>>>(cnt_a, ptr_a, NA);
    copy_int_kernel<<<divup(NA, TB), TB>>>(cur_a, ptr_a, NA);
    scatter_kernel<<<divup(NE, TB), TB>>>(ha_src, ha_dst, cur_a, csr_ha, NE);

    // ---- Layer 1 ----
    agg_mean_kernel<<<divup(NH * 32, TB), TB>>>(x_a, ptr_h, csr_ah, agg_h, NH);
    gemm256_kernel<<<divup(NH, 64), TB>>>(agg_h, D, x_h, D, W1_ah_l, W1_ah_r, b1_ah, h_h, D, NH, 1);
    agg_mean_kernel<<<divup(NA * 32, TB), TB>>>(x_h, ptr_a, csr_ha, agg_a, NA);
    gemm256_kernel<<<divup(NA, 64), TB>>>(agg_a, D, x_a, D, W1_ha_l, W1_ha_r, b1_ha, h_a, D, NA, 1);

    // ---- Layer 2 ----
    agg_mean_kernel<<<divup(NH * 32, TB), TB>>>(h_a, ptr_h, csr_ah, agg_h, NH);
    gemm256_kernel<<<divup(NH, 64), TB>>>(agg_h, D, h_h, D, W2_ah_l, W2_ah_r, b2_ah, z_h, D, NH, 0);
    agg_mean_kernel<<<divup(NA * 32, TB), TB>>>(h_h, ptr_a, csr_ha, agg_a, NA);
    gemm256_kernel<<<divup(NA, 64), TB>>>(agg_a, D, h_a, D, W2_ha_l, W2_ha_r, b2_ha, z_a, D, NA, 0);

    // ---- Decoder ----
    gather_z1_kernel<<<divup(EL * 32, TB), TB>>>(z_a, z_h, e_row, e_col, z1, EL);
    gemm256_kernel<<<divup(EL, 64), TB>>>(z1, 256, z1 + 128, 256, W_lin1, W_lin1 + 128 * 128,
                                          b_lin1, z2, D, EL, 1);
    pred_kernel<<<divup(EL * 32, TB), TB>>>(z2, W_lin2, b_lin2, pred, EL);
}

// round 14
// speedup vs baseline: 1.8136x; 1.8131x over previous
#include <cuda_runtime.h>
#include <cstdint>

#define NA 100000
#define NH 20000
#define NE 1000000
#define EL 200000
#define D  128

// ---------------- device scratch (static, no allocations) ----------------
__device__ int   g_cnt_a[NA];
__device__ int   g_cnt_h[NH];
__device__ int   g_ptr_a[NA + 1];
__device__ int   g_ptr_h[NH + 1];
__device__ int   g_cur_a[NA];
__device__ int   g_cur_h[NH];
__device__ int   g_csr_ah[NE];
__device__ int   g_csr_ha[NE];
__device__ float g_agg_a[(size_t)NA * D];
__device__ float g_agg_h[(size_t)NH * D];
__device__ float g_h_a[(size_t)NA * D];
__device__ float g_h_h[(size_t)NH * D];
__device__ float g_z_a[(size_t)NA * D];
__device__ float g_z_h[(size_t)NH * D];
// transposed + bf16 hi/lo split weights: 5 configs x {hi,lo} x [128 n][256 k] bf16
__device__ uint16_t g_wt[5][2][128 * 256];

// ---------------- PTX helpers (sm_80-compatible only; NO tcgen05) ----------------
__device__ __forceinline__ uint32_t smem_u32(const void* p) {
    uint32_t a;
    asm("{ .reg .u64 t; cvta.to.shared.u64 t, %1; cvt.u32.u64 %0, t; }" : "=r"(a) : "l"(p));
    return a;
}
// pack two fp32 into bf16x2: element0 (low 16 bits) = lo_elem, element1 = hi_elem
__device__ __forceinline__ uint32_t pack_bf16x2(float hi_elem, float lo_elem) {
    uint32_t d;
    asm("cvt.rn.bf16x2.f32 %0, %1, %2;" : "=r"(d) : "f"(hi_elem), "f"(lo_elem));
    return d;
}
__device__ __forceinline__ float bf16_lo_as_f32(uint32_t p) { return __uint_as_float(p << 16); }
__device__ __forceinline__ float bf16_hi_as_f32(uint32_t p) { return __uint_as_float(p & 0xFFFF0000u); }

#define LDSM_X4(r, addr) \
    asm volatile("ldmatrix.sync.aligned.m8n8.x4.shared.b16 {%0,%1,%2,%3}, [%4];" \
        : "=r"((r)[0]), "=r"((r)[1]), "=r"((r)[2]), "=r"((r)[3]) : "r"(addr))

__device__ __forceinline__ void mma_bf16(float* c, const uint32_t* a, const uint32_t* b) {
    asm volatile(
        "mma.sync.aligned.m16n8k16.row.col.f32.bf16.bf16.f32 "
        "{%0,%1,%2,%3}, {%4,%5,%6,%7}, {%8,%9}, {%0,%1,%2,%3};"
        : "+f"(c[0]), "+f"(c[1]), "+f"(c[2]), "+f"(c[3])
        : "r"(a[0]), "r"(a[1]), "r"(a[2]), "r"(a[3]), "r"(b[0]), "r"(b[1]));
}

// ---------------- small utility kernels ----------------
__global__ void zero_int_kernel(int* p, int n) {
    int i = blockIdx.x * blockDim.x + threadIdx.x;
    if (i < n) p[i] = 0;
}
__global__ void copy_int_kernel(int* dst, const int* src, int n) {
    int i = blockIdx.x * blockDim.x + threadIdx.x;
    if (i < n) dst[i] = src[i];
}
__global__ void hist_kernel(const int* __restrict__ dst, int* __restrict__ cnt, int n) {
    int i = blockIdx.x * blockDim.x + threadIdx.x;
    if (i < n) atomicAdd(&cnt[dst[i]], 1);
}
__global__ void scatter_kernel(const int* __restrict__ src, const int* __restrict__ dst,
                               int* __restrict__ cur, int* __restrict__ csr, int n) {
    int i = blockIdx.x * blockDim.x + threadIdx.x;
    if (i < n) {
        int d = dst[i];
        int p = atomicAdd(&cur[d], 1);
        csr[p] = src[i];
    }
}
__global__ void exscan_kernel(const int* __restrict__ cnt, int* __restrict__ ptr, int n) {
    __shared__ int warp_sums[32];
    __shared__ int s_carry;
    int tid = threadIdx.x;
    int lane = tid & 31, wid = tid >> 5;
    if (tid == 0) s_carry = 0;
    __syncthreads();
    for (int base = 0; base < n; base += 1024) {
        int i = base + tid;
        int v = (i < n) ? cnt[i] : 0;
        int x = v;
        #pragma unroll
        for (int o = 1; o < 32; o <<= 1) {
            int y = __shfl_up_sync(0xFFFFFFFFu, x, o);
            if (lane >= o) x += y;
        }
        if (lane == 31) warp_sums[wid] = x;
        __syncthreads();
        if (wid == 0) {
            int s = warp_sums[lane];
            #pragma unroll
            for (int o = 1; o < 32; o <<= 1) {
                int y = __shfl_up_sync(0xFFFFFFFFu, s, o);
                if (lane >= o) s += y;
            }
            warp_sums[lane] = s;
        }
        __syncthreads();
        int incl = x + ((wid > 0) ? warp_sums[wid - 1] : 0);
        int carry = s_carry;
        if (i < n) ptr[i] = carry + incl - v;
        __syncthreads();
        if (tid == 1023) s_carry = carry + incl;
        __syncthreads();
    }
    if (tid == 0) ptr[n] = s_carry;
}

// ---------------- mean aggregation: one warp per destination node ----------------
__global__ void agg_mean_kernel(const float* __restrict__ X,
                                const int* __restrict__ ptr,
                                const int* __restrict__ idx,
                                float* __restrict__ out, int n) {
    int w = (blockIdx.x * blockDim.x + threadIdx.x) >> 5;
    int lane = threadIdx.x & 31;
    if (w >= n) return;
    int s = ptr[w], e = ptr[w + 1];
    float ax = 0.f, ay = 0.f, az = 0.f, aw = 0.f;
    int i = s;
    for (; i + 2 <= e; i += 2) {
        int s0 = __ldg(&idx[i]);
        int s1 = __ldg(&idx[i + 1]);
        float4 v0 = *reinterpret_cast<const float4*>(X + (size_t)s0 * D + lane * 4);
        float4 v1 = *reinterpret_cast<const float4*>(X + (size_t)s1 * D + lane * 4);
        ax += v0.x; ay += v0.y; az += v0.z; aw += v0.w;
        ax += v1.x; ay += v1.y; az += v1.z; aw += v1.w;
    }
    if (i < e) {
        int s0 = __ldg(&idx[i]);
        float4 v0 = *reinterpret_cast<const float4*>(X + (size_t)s0 * D + lane * 4);
        ax += v0.x; ay += v0.y; az += v0.z; aw += v0.w;
    }
    int deg = e - s;
    float inv = 1.0f / (float)(deg > 0 ? deg : 1);
    float4 r = make_float4(ax * inv, ay * inv, az * inv, aw * inv);
    *reinterpret_cast<float4*>(out + (size_t)w * D + lane * 4) = r;
}

// ---------------- weight transpose + bf16 hi/lo split ----------------
// out[n][k] = W[k][n] (k<128 from Wl, else Wr), split into bf16 hi + lo
__global__ void wsplit_kernel(const float* __restrict__ Wl, const float* __restrict__ Wr,
                              uint16_t* __restrict__ hi, uint16_t* __restrict__ lo) {
    int idx = blockIdx.x * blockDim.x + threadIdx.x;
    if (idx >= 128 * 256) return;
    int n = idx >> 8;
    int k = idx & 255;
    float v = (k < 128) ? Wl[(size_t)k * 128 + n] : Wr[(size_t)(k - 128) * 128 + n];
    uint32_t h = pack_bf16x2(0.f, v);           // low half = bf16(v)
    float hf = bf16_lo_as_f32(h);
    uint32_t l = pack_bf16x2(0.f, v - hf);
    hi[idx] = (uint16_t)(h & 0xFFFF);
    lo[idx] = (uint16_t)(l & 0xFFFF);
}

// ---------------- bf16-split tensor-core GEMM (mma.sync) ----------------
// C[M,128] = [A0 | A1] (K=256) @ Wt^T + bias, optional relu.
// Wt hi/lo: [128 n][256 k] bf16, pre-transposed & split.
// CTA tile 128x128, 8 warps in 2(M)x4(N), warp tile 64x32, K chunk = 32.
// SMEM row stride 112B (16B aligned; ldmatrix bank-conflict-free).
#define TSTRIDE 112
#define TILE_BYTES (128 * TSTRIDE)          // 14336
#define STAGE_BYTES (4 * TILE_BYTES)        // A_hi A_lo B_hi B_lo = 57344
#define GSM_BYTES (2 * STAGE_BYTES + 256)

__global__ void __launch_bounds__(256, 1)
gemm_mma_kernel(const float* __restrict__ A0, int lda0,
                const float* __restrict__ A1, int lda1,
                const uint16_t* __restrict__ Whi, const uint16_t* __restrict__ Wlo,
                const float* __restrict__ bias,
                float* __restrict__ C, int ldc, int M, int relu) {
    extern __shared__ char smem[];
    uint32_t tb = (smem_u32(smem) + 127) & ~127u;

    int tid = threadIdx.x;
    int wid = tid >> 5, lane = tid & 31;
    int warpM = wid >> 2;        // 0..1
    int warpN = wid & 3;         // 0..3
    int row0 = blockIdx.x * 128;

    float acc[4][4][4];
    #pragma unroll
    for (int mt = 0; mt < 4; mt++)
        #pragma unroll
        for (int nt = 0; nt < 4; nt++)
            #pragma unroll
            for (int j = 0; j < 4; j++) acc[mt][nt][j] = 0.f;

    // register staging for next chunk
    float4 sA[4];
    uint4  sBh[2], sBl[2];

    // decode per-thread staging coordinates
    // A: p = tid + i*256 -> r = p>>3 (0..127), c = p&7 (k-group of 4 floats)
    // B: p = tid + i*256 -> r = p>>2 (0..127), c = p&3 (k-group of 8 bf16)

    // ---- load chunk kc into regs ----
    #define LD_CHUNK(kc)                                                            \
    do {                                                                            \
        const float* Ap = ((kc) < 4) ? A0 : A1;                                     \
        int lda = ((kc) < 4) ? lda0 : lda1;                                         \
        int koff = ((kc) & 3) * 32;                                                 \
        _Pragma("unroll")                                                           \
        for (int i = 0; i < 4; i++) {                                               \
            int p = tid + i * 256;                                                  \
            int r = p >> 3, c = p & 7;                                              \
            int gr = row0 + r;                                                      \
            sA[i] = (gr < M)                                                        \
                ? *reinterpret_cast<const float4*>(Ap + (size_t)gr * lda + koff + c * 4) \
                : make_float4(0.f, 0.f, 0.f, 0.f);                                  \
        }                                                                           \
        _Pragma("unroll")                                                           \
        for (int i = 0; i < 2; i++) {                                               \
            int p = tid + i * 256;                                                  \
            int r = p >> 2, c = p & 3;                                              \
            size_t g = (size_t)r * 256 + (kc) * 32 + c * 8;                         \
            sBh[i] = *reinterpret_cast<const uint4*>(Whi + g);                      \
            sBl[i] = *reinterpret_cast<const uint4*>(Wlo + g);                      \
        }                                                                           \
    } while (0)

    // ---- store staged regs into smem stage s ----
    #define ST_CHUNK(s)                                                             \
    do {                                                                            \
        uint32_t base = tb + (s) * STAGE_BYTES;                                     \
        _Pragma("unroll")                                                           \
        for (int i = 0; i < 4; i++) {                                               \
            int p = tid + i * 256;                                                  \
            int r = p >> 3, c = p & 7;                                              \
            uint32_t h01 = pack_bf16x2(sA[i].y, sA[i].x);                           \
            uint32_t h23 = pack_bf16x2(sA[i].w, sA[i].z);                           \
            float lx = sA[i].x - bf16_lo_as_f32(h01);                               \
            float ly = sA[i].y - bf16_hi_as_f32(h01);                               \
            float lz = sA[i].z - bf16_lo_as_f32(h23);                               \
            float lw = sA[i].w - bf16_hi_as_f32(h23);                               \
            uint32_t l01 = pack_bf16x2(ly, lx);                                     \
            uint32_t l23 = pack_bf16x2(lw, lz);                                     \
            uint32_t ad = base + r * TSTRIDE + c * 8;                               \
            asm volatile("st.shared.v2.b32 [%0], {%1, %2};" :: "r"(ad), "r"(h01), "r"(h23) : "memory"); \
            asm volatile("st.shared.v2.b32 [%0], {%1, %2};" :: "r"(ad + TILE_BYTES), "r"(l01), "r"(l23) : "memory"); \
        }                                                                           \
        _Pragma("unroll")                                                           \
        for (int i = 0; i < 2; i++) {                                               \
            int p = tid + i * 256;                                                  \
            int r = p >> 2, c = p & 3;                                              \
            uint32_t ad = base + 2 * TILE_BYTES + r * TSTRIDE + c * 16;             \
            asm volatile("st.shared.v4.b32 [%0], {%1, %2, %3, %4};"                 \
                :: "r"(ad), "r"(sBh[i].x), "r"(sBh[i].y), "r"(sBh[i].z), "r"(sBh[i].w) : "memory"); \
            asm volatile("st.shared.v4.b32 [%0], {%1, %2, %3, %4};"                 \
                :: "r"(ad + TILE_BYTES), "r"(sBl[i].x), "r"(sBl[i].y), "r"(sBl[i].z), "r"(sBl[i].w) : "memory"); \
        }                                                                           \
    } while (0)

    LD_CHUNK(0);
    ST_CHUNK(0);
    __syncthreads();

    #pragma unroll 1
    for (int kc = 0; kc < 8; ++kc) {
        if (kc < 7) LD_CHUNK(kc + 1);

        // ---- compute on stage kc&1 ----
        {
            uint32_t base = tb + (kc & 1) * STAGE_BYTES;
            uint32_t aBase = base;
            uint32_t bBase = base + 2 * TILE_BYTES;
            #pragma unroll
            for (int ks = 0; ks < 2; ks++) {
                uint32_t Af[2][4][4];
                #pragma unroll
                for (int mt = 0; mt < 4; mt++) {
                    uint32_t ad = aBase + (warpM * 64 + mt * 16 + (lane & 15)) * TSTRIDE
                                + ks * 32 + (lane >> 4) * 16;
                    LDSM_X4(Af[0][mt], ad);
                    LDSM_X4(Af[1][mt], ad + TILE_BYTES);
                }
                uint32_t Bf[2][4][2];
                #pragma unroll
                for (int ng = 0; ng < 2; ng++) {
                    uint32_t ad = bBase + (warpN * 32 + ng * 16 + (lane & 15)) * TSTRIDE
                                + ks * 32 + (lane >> 4) * 16;
                    uint32_t r[4];
                    LDSM_X4(r, ad);
                    Bf[0][ng * 2][0] = r[0]; Bf[0][ng * 2][1] = r[2];
                    Bf[0][ng * 2 + 1][0] = r[1]; Bf[0][ng * 2 + 1][1] = r[3];
                    LDSM_X4(r, ad + TILE_BYTES);
                    Bf[1][ng * 2][0] = r[0]; Bf[1][ng * 2][1] = r[2];
                    Bf[1][ng * 2 + 1][0] = r[1]; Bf[1][ng * 2 + 1][1] = r[3];
                }
                #pragma unroll
                for (int mt = 0; mt < 4; mt++)
                    #pragma unroll
                    for (int nt = 0; nt < 4; nt++) {
                        mma_bf16(acc[mt][nt], Af[0][mt], Bf[0][nt]);   // hi*hi
                        mma_bf16(acc[mt][nt], Af[0][mt], Bf[1][nt]);   // hi*lo
                        mma_bf16(acc[mt][nt], Af[1][mt], Bf[0][nt]);   // lo*hi
                    }
            }
        }

        __syncthreads();
        if (kc < 7) {
            ST_CHUNK((kc + 1) & 1);
            __syncthreads();
        }
    }

    // ---- epilogue ----
    #pragma unroll
    for (int mt = 0; mt < 4; mt++) {
        int rg = row0 + warpM * 64 + mt * 16 + (lane >> 2);
        #pragma unroll
        for (int nt = 0; nt < 4; nt++) {
            int col = warpN * 32 + nt * 8 + ((lane & 3) << 1);
            float2 bv = *reinterpret_cast<const float2*>(bias + col);
            float2 o0, o1;
            o0.x = acc[mt][nt][0] + bv.x; o0.y = acc[mt][nt][1] + bv.y;
            o1.x = acc[mt][nt][2] + bv.x; o1.y = acc[mt][nt][3] + bv.y;
            if (relu) {
                o0.x = fmaxf(o0.x, 0.f); o0.y = fmaxf(o0.y, 0.f);
                o1.x = fmaxf(o1.x, 0.f); o1.y = fmaxf(o1.y, 0.f);
            }
            if (rg < M)     *reinterpret_cast<float2*>(C + (size_t)rg * ldc + col) = o0;
            if (rg + 8 < M) *reinterpret_cast<float2*>(C + (size_t)(rg + 8) * ldc + col) = o1;
        }
    }
    #undef LD_CHUNK
    #undef ST_CHUNK
}

// ---------------- decoder: gather z1 rows (one warp per link edge) ----------------
__global__ void gather_z1_kernel(const float* __restrict__ za, const float* __restrict__ zh,
                                 const int* __restrict__ row, const int* __restrict__ col,
                                 float* __restrict__ z1, int n) {
    int w = (blockIdx.x * blockDim.x + threadIdx.x) >> 5;
    int lane = threadIdx.x & 31;
    if (w >= n) return;
    int r = __ldg(&row[w]);
    int c = __ldg(&col[w]);
    float4 a = *reinterpret_cast<const float4*>(za + (size_t)r * D + lane * 4);
    float4 b = *reinterpret_cast<const float4*>(zh + (size_t)c * D + lane * 4);
    *reinterpret_cast<float4*>(z1 + (size_t)w * 256 + lane * 4)       = a;
    *reinterpret_cast<float4*>(z1 + (size_t)w * 256 + 128 + lane * 4) = b;
}

// ---------------- pred = z2 @ W_lin2 + b_lin2 (one warp per row) ----------------
__global__ void pred_kernel(const float* __restrict__ z2, const float* __restrict__ w2,
                            const float* __restrict__ b2, float* __restrict__ out, int n) {
    int w = (blockIdx.x * blockDim.x + threadIdx.x) >> 5;
    int lane = threadIdx.x & 31;
    if (w >= n) return;
    float4 v  = *reinterpret_cast<const float4*>(z2 + (size_t)w * D + lane * 4);
    float4 ww = *reinterpret_cast<const float4*>(w2 + lane * 4);
    float s = v.x * ww.x + v.y * ww.y + v.z * ww.z + v.w * ww.w;
    #pragma unroll
    for (int o = 16; o > 0; o >>= 1) s += __shfl_xor_sync(0xFFFFFFFFu, s, o);
    if (lane == 0) out[w] = s + b2[0];
}

// ---------------- host launch ----------------
static inline int divup(int a, int b) { return (a + b - 1) / b; }

extern "C" void kernel_launch(void* const* d_in, const int* in_sizes, int n_in,
                              void* d_out, int out_size) {
    const float* x_a    = (const float*)d_in[0];
    const float* x_h    = (const float*)d_in[1];
    const int*   ah_src = (const int*)d_in[2];
    const int*   ah_dst = (const int*)d_in[3];
    const int*   ha_src = (const int*)d_in[4];
    const int*   ha_dst = (const int*)d_in[5];
    const int*   e_row  = (const int*)d_in[6];
    const int*   e_col  = (const int*)d_in[7];

    bool sig = (in_sizes[9] == 128);
    const float *W1_ah_l, *W1_ah_r, *W1_ha_l, *W1_ha_r;
    const float *W2_ah_l, *W2_ah_r, *W2_ha_l, *W2_ha_r;
    const float *b1_ah, *b1_ha, *b2_ah, *b2_ha;
    if (sig) {
        W1_ah_l = (const float*)d_in[8];  b1_ah = (const float*)d_in[9];
        W1_ah_r = (const float*)d_in[10];
        W1_ha_l = (const float*)d_in[11]; b1_ha = (const float*)d_in[12];
        W1_ha_r = (const float*)d_in[13];
        W2_ah_l = (const float*)d_in[14]; b2_ah = (const float*)d_in[15];
        W2_ah_r = (const float*)d_in[16];
        W2_ha_l = (const float*)d_in[17]; b2_ha = (const float*)d_in[18];
        W2_ha_r = (const float*)d_in[19];
    } else {
        W1_ah_l = (const float*)d_in[8];  W1_ah_r = (const float*)d_in[9];
        W1_ha_l = (const float*)d_in[10]; W1_ha_r = (const float*)d_in[11];
        W2_ah_l = (const float*)d_in[12]; W2_ah_r = (const float*)d_in[13];
        W2_ha_l = (const float*)d_in[14]; W2_ha_r = (const float*)d_in[15];
        b1_ah = (const float*)d_in[16];   b1_ha = (const float*)d_in[17];
        b2_ah = (const float*)d_in[18];   b2_ha = (const float*)d_in[19];
    }
    const float* W_lin1 = (const float*)d_in[20];
    const float* b_lin1 = (const float*)d_in[21];
    const float* W_lin2 = (const float*)d_in[22];
    const float* b_lin2 = (const float*)d_in[23];

    float* out  = (float*)d_out;
    float* pred = out;
    float* z1   = out + EL;
    float* z2   = out + EL + (size_t)EL * 256;

    int *cnt_a, *cnt_h, *ptr_a, *ptr_h, *cur_a, *cur_h, *csr_ah, *csr_ha;
    float *agg_a, *agg_h, *h_a, *h_h, *z_a, *z_h;
    uint16_t* wt;
    cudaGetSymbolAddress((void**)&cnt_a, g_cnt_a);
    cudaGetSymbolAddress((void**)&cnt_h, g_cnt_h);
    cudaGetSymbolAddress((void**)&ptr_a, g_ptr_a);
    cudaGetSymbolAddress((void**)&ptr_h, g_ptr_h);
    cudaGetSymbolAddress((void**)&cur_a, g_cur_a);
    cudaGetSymbolAddress((void**)&cur_h, g_cur_h);
    cudaGetSymbolAddress((void**)&csr_ah, g_csr_ah);
    cudaGetSymbolAddress((void**)&csr_ha, g_csr_ha);
    cudaGetSymbolAddress((void**)&agg_a, g_agg_a);
    cudaGetSymbolAddress((void**)&agg_h, g_agg_h);
    cudaGetSymbolAddress((void**)&h_a, g_h_a);
    cudaGetSymbolAddress((void**)&h_h, g_h_h);
    cudaGetSymbolAddress((void**)&z_a, g_z_a);
    cudaGetSymbolAddress((void**)&z_h, g_z_h);
    cudaGetSymbolAddress((void**)&wt, g_wt);

    const int WSZ = 128 * 256;
    uint16_t* wt_hi[5]; uint16_t* wt_lo[5];
    for (int i = 0; i < 5; i++) { wt_hi[i] = wt + (size_t)i * 2 * WSZ; wt_lo[i] = wt_hi[i] + WSZ; }

    cudaFuncSetAttribute(gemm_mma_kernel, cudaFuncAttributeMaxDynamicSharedMemorySize, GSM_BYTES);

    const int TB = 256;

    // ---- weight transpose + split ----
    wsplit_kernel<<<divup(WSZ, TB), TB>>>(W1_ah_l, W1_ah_r, wt_hi[0], wt_lo[0]);
    wsplit_kernel<<<divup(WSZ, TB), TB>>>(W1_ha_l, W1_ha_r, wt_hi[1], wt_lo[1]);
    wsplit_kernel<<<divup(WSZ, TB), TB>>>(W2_ah_l, W2_ah_r, wt_hi[2], wt_lo[2]);
    wsplit_kernel<<<divup(WSZ, TB), TB>>>(W2_ha_l, W2_ha_r, wt_hi[3], wt_lo[3]);
    wsplit_kernel<<<divup(WSZ, TB), TB>>>(W_lin1, W_lin1 + 128 * 128, wt_hi[4], wt_lo[4]);

    // ---- CSR build: a->h edges grouped by hotel dst ----
    zero_int_kernel<<<divup(NH, TB), TB>>>(cnt_h, NH);
    hist_kernel<<<divup(NE, TB), TB>>>(ah_dst, cnt_h, NE);
    exscan_kernel<<<1, 1024>>>(cnt_h, ptr_h, NH);
    copy_int_kernel<<<divup(NH, TB), TB>>>(cur_h, ptr_h, NH);
    scatter_kernel<<<divup(NE, TB), TB>>>(ah_src, ah_dst, cur_h, csr_ah, NE);

    // ---- CSR build: h->a edges grouped by author dst ----
    zero_int_kernel<<<divup(NA, TB), TB>>>(cnt_a, NA);
    hist_kernel<<<divup(NE, TB), TB>>>(ha_dst, cnt_a, NE);
    exscan_kernel<<<1, 1024>>>(cnt_a, ptr_a, NA);
    copy_int_kernel<<<divup(NA, TB), TB>>>(cur_a, ptr_a, NA);
    scatter_kernel<<<divup(NE, TB), TB>>>(ha_src, ha_dst, cur_a, csr_ha, NE);

    // ---- Layer 1 ----
    agg_mean_kernel<<<divup(NH * 32, TB), TB>>>(x_a, ptr_h, csr_ah, agg_h, NH);
    gemm_mma_kernel<<<divup(NH, 128), TB, GSM_BYTES>>>(agg_h, D, x_h, D, wt_hi[0], wt_lo[0], b1_ah, h_h, D, NH, 1);
    agg_mean_kernel<<<divup(NA * 32, TB), TB>>>(x_h, ptr_a, csr_ha, agg_a, NA);
    gemm_mma_kernel<<<divup(NA, 128), TB, GSM_BYTES>>>(agg_a, D, x_a, D, wt_hi[1], wt_lo[1], b1_ha, h_a, D, NA, 1);

    // ---- Layer 2 ----
    agg_mean_kernel<<<divup(NH * 32, TB), TB>>>(h_a, ptr_h, csr_ah, agg_h, NH);
    gemm_mma_kernel<<<divup(NH, 128), TB, GSM_BYTES>>>(agg_h, D, h_h, D, wt_hi[2], wt_lo[2], b2_ah, z_h, D, NH, 0);
    agg_mean_kernel<<<divup(NA * 32, TB), TB>>>(h_h, ptr_a, csr_ha, agg_a, NA);
    gemm_mma_kernel<<<divup(NA, 128), TB, GSM_BYTES>>>(agg_a, D, h_a, D, wt_hi[3], wt_lo[3], b2_ha, z_a, D, NA, 0);

    // ---- Decoder ----
    gather_z1_kernel<<<divup(EL * 32, TB), TB>>>(z_a, z_h, e_row, e_col, z1, EL);
    gemm_mma_kernel<<<divup(EL, 128), TB, GSM_BYTES>>>(z1, 256, z1 + 128, 256, wt_hi[4], wt_lo[4], b_lin1, z2, D, EL, 1);
    pred_kernel<<<divup(EL * 32, TB), TB>>>(z2, W_lin2, b_lin2, pred, EL);
}

// round 15
// speedup vs baseline: 1.8144x; 1.0004x over previous
#include <cuda_runtime.h>
#include <cstdint>

#define NA 100000
#define NH 20000
#define NE 1000000
#define EL 200000
#define D  128

// ---------------- device scratch (static, no allocations) ----------------
__device__ int   g_cnt_a[NA];
__device__ int   g_cnt_h[NH];
__device__ int   g_ptr_a[NA + 1];
__device__ int   g_ptr_h[NH + 1];
__device__ int   g_cur_a[NA];
__device__ int   g_cur_h[NH];
__device__ int   g_csr_ah[NE];
__device__ int   g_csr_ha[NE];
__device__ float g_agg_a[(size_t)NA * D];
__device__ float g_agg_h[(size_t)NH * D];
__device__ float g_h_a[(size_t)NA * D];
__device__ float g_h_h[(size_t)NH * D];
__device__ float g_z_a[(size_t)NA * D];
__device__ float g_z_h[(size_t)NH * D];
// transposed + bf16 hi/lo split weights: 5 configs x {hi,lo} x [128 n][256 k] bf16
__device__ uint16_t g_wt[5][2][128 * 256];

// ---------------- PTX helpers (sm_80-compatible only; NO tcgen05) ----------------
__device__ __forceinline__ uint32_t smem_u32(const void* p) {
    uint32_t a;
    asm("{ .reg .u64 t; cvta.to.shared.u64 t, %1; cvt.u32.u64 %0, t; }" : "=r"(a) : "l"(p));
    return a;
}
// pack two fp32 into bf16x2: element0 (low 16 bits) = lo_elem, element1 = hi_elem
__device__ __forceinline__ uint32_t pack_bf16x2(float hi_elem, float lo_elem) {
    uint32_t d;
    asm("cvt.rn.bf16x2.f32 %0, %1, %2;" : "=r"(d) : "f"(hi_elem), "f"(lo_elem));
    return d;
}
__device__ __forceinline__ float bf16_lo_as_f32(uint32_t p) { return __uint_as_float(p << 16); }
__device__ __forceinline__ float bf16_hi_as_f32(uint32_t p) { return __uint_as_float(p & 0xFFFF0000u); }

#define LDSM_X4(r, addr) \
    asm volatile("ldmatrix.sync.aligned.m8n8.x4.shared.b16 {%0,%1,%2,%3}, [%4];" \
        : "=r"((r)[0]), "=r"((r)[1]), "=r"((r)[2]), "=r"((r)[3]) : "r"(addr))

__device__ __forceinline__ void mma_bf16(float* c, const uint32_t* a, const uint32_t* b) {
    asm volatile(
        "mma.sync.aligned.m16n8k16.row.col.f32.bf16.bf16.f32 "
        "{%0,%1,%2,%3}, {%4,%5,%6,%7}, {%8,%9}, {%0,%1,%2,%3};"
        : "+f"(c[0]), "+f"(c[1]), "+f"(c[2]), "+f"(c[3])
        : "r"(a[0]), "r"(a[1]), "r"(a[2]), "r"(a[3]), "r"(b[0]), "r"(b[1]));
}

// ---------------- small utility kernels ----------------
__global__ void zero_int_kernel(int* p, int n) {
    int i = blockIdx.x * blockDim.x + threadIdx.x;
    if (i < n) p[i] = 0;
}
__global__ void copy_int_kernel(int* dst, const int* src, int n) {
    int i = blockIdx.x * blockDim.x + threadIdx.x;
    if (i < n) dst[i] = src[i];
}
__global__ void hist_kernel(const int* __restrict__ dst, int* __restrict__ cnt, int n) {
    int i = blockIdx.x * blockDim.x + threadIdx.x;
    if (i < n) atomicAdd(&cnt[dst[i]], 1);
}
__global__ void scatter_kernel(const int* __restrict__ src, const int* __restrict__ dst,
                               int* __restrict__ cur, int* __restrict__ csr, int n) {
    int i = blockIdx.x * blockDim.x + threadIdx.x;
    if (i < n) {
        int d = dst[i];
        int p = atomicAdd(&cur[d], 1);
        csr[p] = src[i];
    }
}
__global__ void exscan_kernel(const int* __restrict__ cnt, int* __restrict__ ptr, int n) {
    __shared__ int warp_sums[32];
    __shared__ int s_carry;
    int tid = threadIdx.x;
    int lane = tid & 31, wid = tid >> 5;
    if (tid == 0) s_carry = 0;
    __syncthreads();
    for (int base = 0; base < n; base += 1024) {
        int i = base + tid;
        int v = (i < n) ? cnt[i] : 0;
        int x = v;
        #pragma unroll
        for (int o = 1; o < 32; o <<= 1) {
            int y = __shfl_up_sync(0xFFFFFFFFu, x, o);
            if (lane >= o) x += y;
        }
        if (lane == 31) warp_sums[wid] = x;
        __syncthreads();
        if (wid == 0) {
            int s = warp_sums[lane];
            #pragma unroll
            for (int o = 1; o < 32; o <<= 1) {
                int y = __shfl_up_sync(0xFFFFFFFFu, s, o);
                if (lane >= o) s += y;
            }
            warp_sums[lane] = s;
        }
        __syncthreads();
        int incl = x + ((wid > 0) ? warp_sums[wid - 1] : 0);
        int carry = s_carry;
        if (i < n) ptr[i] = carry + incl - v;
        __syncthreads();
        if (tid == 1023) s_carry = carry + incl;
        __syncthreads();
    }
    if (tid == 0) ptr[n] = s_carry;
}

// ---------------- mean aggregation: one warp per destination node ----------------
__global__ void agg_mean_kernel(const float* __restrict__ X,
                                const int* __restrict__ ptr,
                                const int* __restrict__ idx,
                                float* __restrict__ out, int n) {
    int w = (blockIdx.x * blockDim.x + threadIdx.x) >> 5;
    int lane = threadIdx.x & 31;
    if (w >= n) return;
    int s = ptr[w], e = ptr[w + 1];
    float ax = 0.f, ay = 0.f, az = 0.f, aw = 0.f;
    int i = s;
    for (; i + 2 <= e; i += 2) {
        int s0 = __ldg(&idx[i]);
        int s1 = __ldg(&idx[i + 1]);
        float4 v0 = *reinterpret_cast<const float4*>(X + (size_t)s0 * D + lane * 4);
        float4 v1 = *reinterpret_cast<const float4*>(X + (size_t)s1 * D + lane * 4);
        ax += v0.x; ay += v0.y; az += v0.z; aw += v0.w;
        ax += v1.x; ay += v1.y; az += v1.z; aw += v1.w;
    }
    if (i < e) {
        int s0 = __ldg(&idx[i]);
        float4 v0 = *reinterpret_cast<const float4*>(X + (size_t)s0 * D + lane * 4);
        ax += v0.x; ay += v0.y; az += v0.z; aw += v0.w;
    }
    int deg = e - s;
    float inv = 1.0f / (float)(deg > 0 ? deg : 1);
    float4 r = make_float4(ax * inv, ay * inv, az * inv, aw * inv);
    *reinterpret_cast<float4*>(out + (size_t)w * D + lane * 4) = r;
}

// ---------------- weight transpose + bf16 hi/lo split ----------------
// out[n][k] = W[k][n] (k<128 from Wl, else Wr), split into bf16 hi + lo
__global__ void wsplit_kernel(const float* __restrict__ Wl, const float* __restrict__ Wr,
                              uint16_t* __restrict__ hi, uint16_t* __restrict__ lo) {
    int idx = blockIdx.x * blockDim.x + threadIdx.x;
    if (idx >= 128 * 256) return;
    int n = idx >> 8;
    int k = idx & 255;
    float v = (k < 128) ? Wl[(size_t)k * 128 + n] : Wr[(size_t)(k - 128) * 128 + n];
    uint32_t h = pack_bf16x2(0.f, v);           // low half = bf16(v)
    float hf = bf16_lo_as_f32(h);
    uint32_t l = pack_bf16x2(0.f, v - hf);
    hi[idx] = (uint16_t)(h & 0xFFFF);
    lo[idx] = (uint16_t)(l & 0xFFFF);
}

// ---------------- bf16-split tensor-core GEMM (mma.sync) ----------------
// C[M,128] = [A0 | A1] (K=256) @ Wt^T + bias, optional relu.
// Wt hi/lo: [128 n][256 k] bf16, pre-transposed & split.
// CTA tile 128x128, 8 warps in 2(M)x4(N), warp tile 64x32, K chunk = 32.
// SMEM row stride 112B (16B aligned; ldmatrix bank-conflict-free).
#define TSTRIDE 112
#define TILE_BYTES (128 * TSTRIDE)          // 14336
#define STAGE_BYTES (4 * TILE_BYTES)        // A_hi A_lo B_hi B_lo = 57344
#define GSM_BYTES (2 * STAGE_BYTES + 256)

__global__ void __launch_bounds__(256, 1)
gemm_mma_kernel(const float* __restrict__ A0, int lda0,
                const float* __restrict__ A1, int lda1,
                const uint16_t* __restrict__ Whi, const uint16_t* __restrict__ Wlo,
                const float* __restrict__ bias,
                float* __restrict__ C, int ldc, int M, int relu) {
    extern __shared__ char smem[];
    uint32_t tb = (smem_u32(smem) + 127) & ~127u;

    int tid = threadIdx.x;
    int wid = tid >> 5, lane = tid & 31;
    int warpM = wid >> 2;        // 0..1
    int warpN = wid & 3;         // 0..3
    int row0 = blockIdx.x * 128;

    float acc[4][4][4];
    #pragma unroll
    for (int mt = 0; mt < 4; mt++)
        #pragma unroll
        for (int nt = 0; nt < 4; nt++)
            #pragma unroll
            for (int j = 0; j < 4; j++) acc[mt][nt][j] = 0.f;

    // register staging for next chunk
    float4 sA[4];
    uint4  sBh[2], sBl[2];

    // decode per-thread staging coordinates
    // A: p = tid + i*256 -> r = p>>3 (0..127), c = p&7 (k-group of 4 floats)
    // B: p = tid + i*256 -> r = p>>2 (0..127), c = p&3 (k-group of 8 bf16)

    // ---- load chunk kc into regs ----
    #define LD_CHUNK(kc)                                                            \
    do {                                                                            \
        const float* Ap = ((kc) < 4) ? A0 : A1;                                     \
        int lda = ((kc) < 4) ? lda0 : lda1;                                         \
        int koff = ((kc) & 3) * 32;                                                 \
        _Pragma("unroll")                                                           \
        for (int i = 0; i < 4; i++) {                                               \
            int p = tid + i * 256;                                                  \
            int r = p >> 3, c = p & 7;                                              \
            int gr = row0 + r;                                                      \
            sA[i] = (gr < M)                                                        \
                ? *reinterpret_cast<const float4*>(Ap + (size_t)gr * lda + koff + c * 4) \
                : make_float4(0.f, 0.f, 0.f, 0.f);                                  \
        }                                                                           \
        _Pragma("unroll")                                                           \
        for (int i = 0; i < 2; i++) {                                               \
            int p = tid + i * 256;                                                  \
            int r = p >> 2, c = p & 3;                                              \
            size_t g = (size_t)r * 256 + (kc) * 32 + c * 8;                         \
            sBh[i] = *reinterpret_cast<const uint4*>(Whi + g);                      \
            sBl[i] = *reinterpret_cast<const uint4*>(Wlo + g);                      \
        }                                                                           \
    } while (0)

    // ---- store staged regs into smem stage s ----
    #define ST_CHUNK(s)                                                             \
    do {                                                                            \
        uint32_t base = tb + (s) * STAGE_BYTES;                                     \
        _Pragma("unroll")                                                           \
        for (int i = 0; i < 4; i++) {                                               \
            int p = tid + i * 256;                                                  \
            int r = p >> 3, c = p & 7;                                              \
            uint32_t h01 = pack_bf16x2(sA[i].y, sA[i].x);                           \
            uint32_t h23 = pack_bf16x2(sA[i].w, sA[i].z);                           \
            float lx = sA[i].x - bf16_lo_as_f32(h01);                               \
            float ly = sA[i].y - bf16_hi_as_f32(h01);                               \
            float lz = sA[i].z - bf16_lo_as_f32(h23);                               \
            float lw = sA[i].w - bf16_hi_as_f32(h23);                               \
            uint32_t l01 = pack_bf16x2(ly, lx);                                     \
            uint32_t l23 = pack_bf16x2(lw, lz);                                     \
            uint32_t ad = base + r * TSTRIDE + c * 8;                               \
            asm volatile("st.shared.v2.b32 [%0], {%1, %2};" :: "r"(ad), "r"(h01), "r"(h23) : "memory"); \
            asm volatile("st.shared.v2.b32 [%0], {%1, %2};" :: "r"(ad + TILE_BYTES), "r"(l01), "r"(l23) : "memory"); \
        }                                                                           \
        _Pragma("unroll")                                                           \
        for (int i = 0; i < 2; i++) {                                               \
            int p = tid + i * 256;                                                  \
            int r = p >> 2, c = p & 3;                                              \
            uint32_t ad = base + 2 * TILE_BYTES + r * TSTRIDE + c * 16;             \
            asm volatile("st.shared.v4.b32 [%0], {%1, %2, %3, %4};"                 \
                :: "r"(ad), "r"(sBh[i].x), "r"(sBh[i].y), "r"(sBh[i].z), "r"(sBh[i].w) : "memory"); \
            asm volatile("st.shared.v4.b32 [%0], {%1, %2, %3, %4};"                 \
                :: "r"(ad + TILE_BYTES), "r"(sBl[i].x), "r"(sBl[i].y), "r"(sBl[i].z), "r"(sBl[i].w) : "memory"); \
        }                                                                           \
    } while (0)

    LD_CHUNK(0);
    ST_CHUNK(0);
    __syncthreads();

    #pragma unroll 1
    for (int kc = 0; kc < 8; ++kc) {
        if (kc < 7) LD_CHUNK(kc + 1);

        // ---- compute on stage kc&1 ----
        {
            uint32_t base = tb + (kc & 1) * STAGE_BYTES;
            uint32_t aBase = base;
            uint32_t bBase = base + 2 * TILE_BYTES;
            #pragma unroll
            for (int ks = 0; ks < 2; ks++) {
                uint32_t Af[2][4][4];
                #pragma unroll
                for (int mt = 0; mt < 4; mt++) {
                    uint32_t ad = aBase + (warpM * 64 + mt * 16 + (lane & 15)) * TSTRIDE
                                + ks * 32 + (lane >> 4) * 16;
                    LDSM_X4(Af[0][mt], ad);
                    LDSM_X4(Af[1][mt], ad + TILE_BYTES);
                }
                uint32_t Bf[2][4][2];
                #pragma unroll
                for (int ng = 0; ng < 2; ng++) {
                    uint32_t ad = bBase + (warpN * 32 + ng * 16 + (lane & 15)) * TSTRIDE
                                + ks * 32 + (lane >> 4) * 16;
                    uint32_t r[4];
                    LDSM_X4(r, ad);
                    Bf[0][ng * 2][0] = r[0]; Bf[0][ng * 2][1] = r[2];
                    Bf[0][ng * 2 + 1][0] = r[1]; Bf[0][ng * 2 + 1][1] = r[3];
                    LDSM_X4(r, ad + TILE_BYTES);
                    Bf[1][ng * 2][0] = r[0]; Bf[1][ng * 2][1] = r[2];
                    Bf[1][ng * 2 + 1][0] = r[1]; Bf[1][ng * 2 + 1][1] = r[3];
                }
                #pragma unroll
                for (int mt = 0; mt < 4; mt++)
                    #pragma unroll
                    for (int nt = 0; nt < 4; nt++) {
                        mma_bf16(acc[mt][nt], Af[0][mt], Bf[0][nt]);   // hi*hi
                        mma_bf16(acc[mt][nt], Af[0][mt], Bf[1][nt]);   // hi*lo
                        mma_bf16(acc[mt][nt], Af[1][mt], Bf[0][nt]);   // lo*hi
                    }
            }
        }

        __syncthreads();
        if (kc < 7) {
            ST_CHUNK((kc + 1) & 1);
            __syncthreads();
        }
    }

    // ---- epilogue ----
    #pragma unroll
    for (int mt = 0; mt < 4; mt++) {
        int rg = row0 + warpM * 64 + mt * 16 + (lane >> 2);
        #pragma unroll
        for (int nt = 0; nt < 4; nt++) {
            int col = warpN * 32 + nt * 8 + ((lane & 3) << 1);
            float2 bv = *reinterpret_cast<const float2*>(bias + col);
            float2 o0, o1;
            o0.x = acc[mt][nt][0] + bv.x; o0.y = acc[mt][nt][1] + bv.y;
            o1.x = acc[mt][nt][2] + bv.x; o1.y = acc[mt][nt][3] + bv.y;
            if (relu) {
                o0.x = fmaxf(o0.x, 0.f); o0.y = fmaxf(o0.y, 0.f);
                o1.x = fmaxf(o1.x, 0.f); o1.y = fmaxf(o1.y, 0.f);
            }
            if (rg < M)     *reinterpret_cast<float2*>(C + (size_t)rg * ldc + col) = o0;
            if (rg + 8 < M) *reinterpret_cast<float2*>(C + (size_t)(rg + 8) * ldc + col) = o1;
        }
    }
    #undef LD_CHUNK
    #undef ST_CHUNK
}

// ---------------- decoder: gather z1 rows (one warp per link edge) ----------------
__global__ void gather_z1_kernel(const float* __restrict__ za, const float* __restrict__ zh,
                                 const int* __restrict__ row, const int* __restrict__ col,
                                 float* __restrict__ z1, int n) {
    int w = (blockIdx.x * blockDim.x + threadIdx.x) >> 5;
    int lane = threadIdx.x & 31;
    if (w >= n) return;
    int r = __ldg(&row[w]);
    int c = __ldg(&col[w]);
    float4 a = *reinterpret_cast<const float4*>(za + (size_t)r * D + lane * 4);
    float4 b = *reinterpret_cast<const float4*>(zh + (size_t)c * D + lane * 4);
    *reinterpret_cast<float4*>(z1 + (size_t)w * 256 + lane * 4)       = a;
    *reinterpret_cast<float4*>(z1 + (size_t)w * 256 + 128 + lane * 4) = b;
}

// ---------------- pred = z2 @ W_lin2 + b_lin2 (one warp per row) ----------------
__global__ void pred_kernel(const float* __restrict__ z2, const float* __restrict__ w2,
                            const float* __restrict__ b2, float* __restrict__ out, int n) {
    int w = (blockIdx.x * blockDim.x + threadIdx.x) >> 5;
    int lane = threadIdx.x & 31;
    if (w >= n) return;
    float4 v  = *reinterpret_cast<const float4*>(z2 + (size_t)w * D + lane * 4);
    float4 ww = *reinterpret_cast<const float4*>(w2 + lane * 4);
    float s = v.x * ww.x + v.y * ww.y + v.z * ww.z + v.w * ww.w;
    #pragma unroll
    for (int o = 16; o > 0; o >>= 1) s += __shfl_xor_sync(0xFFFFFFFFu, s, o);
    if (lane == 0) out[w] = s + b2[0];
}

// ---------------- host launch ----------------
static inline int divup(int a, int b) { return (a + b - 1) / b; }

extern "C" void kernel_launch(void* const* d_in, const int* in_sizes, int n_in,
                              void* d_out, int out_size) {
    const float* x_a    = (const float*)d_in[0];
    const float* x_h    = (const float*)d_in[1];
    const int*   ah_src = (const int*)d_in[2];
    const int*   ah_dst = (const int*)d_in[3];
    const int*   ha_src = (const int*)d_in[4];
    const int*   ha_dst = (const int*)d_in[5];
    const int*   e_row  = (const int*)d_in[6];
    const int*   e_col  = (const int*)d_in[7];

    bool sig = (in_sizes[9] == 128);
    const float *W1_ah_l, *W1_ah_r, *W1_ha_l, *W1_ha_r;
    const float *W2_ah_l, *W2_ah_r, *W2_ha_l, *W2_ha_r;
    const float *b1_ah, *b1_ha, *b2_ah, *b2_ha;
    if (sig) {
        W1_ah_l = (const float*)d_in[8];  b1_ah = (const float*)d_in[9];
        W1_ah_r = (const float*)d_in[10];
        W1_ha_l = (const float*)d_in[11]; b1_ha = (const float*)d_in[12];
        W1_ha_r = (const float*)d_in[13];
        W2_ah_l = (const float*)d_in[14]; b2_ah = (const float*)d_in[15];
        W2_ah_r = (const float*)d_in[16];
        W2_ha_l = (const float*)d_in[17]; b2_ha = (const float*)d_in[18];
        W2_ha_r = (const float*)d_in[19];
    } else {
        W1_ah_l = (const float*)d_in[8];  W1_ah_r = (const float*)d_in[9];
        W1_ha_l = (const float*)d_in[10]; W1_ha_r = (const float*)d_in[11];
        W2_ah_l = (const float*)d_in[12]; W2_ah_r = (const float*)d_in[13];
        W2_ha_l = (const float*)d_in[14]; W2_ha_r = (const float*)d_in[15];
        b1_ah = (const float*)d_in[16];   b1_ha = (const float*)d_in[17];
        b2_ah = (const float*)d_in[18];   b2_ha = (const float*)d_in[19];
    }
    const float* W_lin1 = (const float*)d_in[20];
    const float* b_lin1 = (const float*)d_in[21];
    const float* W_lin2 = (const float*)d_in[22];
    const float* b_lin2 = (const float*)d_in[23];

    float* out  = (float*)d_out;
    float* pred = out;
    float* z1   = out + EL;
    float* z2   = out + EL + (size_t)EL * 256;

    int *cnt_a, *cnt_h, *ptr_a, *ptr_h, *cur_a, *cur_h, *csr_ah, *csr_ha;
    float *agg_a, *agg_h, *h_a, *h_h, *z_a, *z_h;
    uint16_t* wt;
    cudaGetSymbolAddress((void**)&cnt_a, g_cnt_a);
    cudaGetSymbolAddress((void**)&cnt_h, g_cnt_h);
    cudaGetSymbolAddress((void**)&ptr_a, g_ptr_a);
    cudaGetSymbolAddress((void**)&ptr_h, g_ptr_h);
    cudaGetSymbolAddress((void**)&cur_a, g_cur_a);
    cudaGetSymbolAddress((void**)&cur_h, g_cur_h);
    cudaGetSymbolAddress((void**)&csr_ah, g_csr_ah);
    cudaGetSymbolAddress((void**)&csr_ha, g_csr_ha);
    cudaGetSymbolAddress((void**)&agg_a, g_agg_a);
    cudaGetSymbolAddress((void**)&agg_h, g_agg_h);
    cudaGetSymbolAddress((void**)&h_a, g_h_a);
    cudaGetSymbolAddress((void**)&h_h, g_h_h);
    cudaGetSymbolAddress((void**)&z_a, g_z_a);
    cudaGetSymbolAddress((void**)&z_h, g_z_h);
    cudaGetSymbolAddress((void**)&wt, g_wt);

    const int WSZ = 128 * 256;
    uint16_t* wt_hi[5]; uint16_t* wt_lo[5];
    for (int i = 0; i < 5; i++) { wt_hi[i] = wt + (size_t)i * 2 * WSZ; wt_lo[i] = wt_hi[i] + WSZ; }

    cudaFuncSetAttribute(gemm_mma_kernel, cudaFuncAttributeMaxDynamicSharedMemorySize, GSM_BYTES);

    const int TB = 256;

    // ---- weight transpose + split ----
    wsplit_kernel<<<divup(WSZ, TB), TB>>>(W1_ah_l, W1_ah_r, wt_hi[0], wt_lo[0]);
    wsplit_kernel<<<divup(WSZ, TB), TB>>>(W1_ha_l, W1_ha_r, wt_hi[1], wt_lo[1]);
    wsplit_kernel<<<divup(WSZ, TB), TB>>>(W2_ah_l, W2_ah_r, wt_hi[2], wt_lo[2]);
    wsplit_kernel<<<divup(WSZ, TB), TB>>>(W2_ha_l, W2_ha_r, wt_hi[3], wt_lo[3]);
    wsplit_kernel<<<divup(WSZ, TB), TB>>>(W_lin1, W_lin1 + 128 * 128, wt_hi[4], wt_lo[4]);

    // ---- CSR build: a->h edges grouped by hotel dst ----
    zero_int_kernel<<<divup(NH, TB), TB>>>(cnt_h, NH);
    hist_kernel<<<divup(NE, TB), TB>>>(ah_dst, cnt_h, NE);
    exscan_kernel<<<1, 1024>>>(cnt_h, ptr_h, NH);
    copy_int_kernel<<<divup(NH, TB), TB>>>(cur_h, ptr_h, NH);
    scatter_kernel<<<divup(NE, TB), TB>>>(ah_src, ah_dst, cur_h, csr_ah, NE);

    // ---- CSR build: h->a edges grouped by author dst ----
    zero_int_kernel<<<divup(NA, TB), TB>>>(cnt_a, NA);
    hist_kernel<<<divup(NE, TB), TB>>>(ha_dst, cnt_a, NE);
    exscan_kernel<<<1, 1024>>>(cnt_a, ptr_a, NA);
    copy_int_kernel<<<divup(NA, TB), TB>>>(cur_a, ptr_a, NA);
    scatter_kernel<<<divup(NE, TB), TB>>>(ha_src, ha_dst, cur_a, csr_ha, NE);

    // ---- Layer 1 ----
    agg_mean_kernel<<<divup(NH * 32, TB), TB>>>(x_a, ptr_h, csr_ah, agg_h, NH);
    gemm_mma_kernel<<<divup(NH, 128), TB, GSM_BYTES>>>(agg_h, D, x_h, D, wt_hi[0], wt_lo[0], b1_ah, h_h, D, NH, 1);
    agg_mean_kernel<<<divup(NA * 32, TB), TB>>>(x_h, ptr_a, csr_ha, agg_a, NA);
    gemm_mma_kernel<<<divup(NA, 128), TB, GSM_BYTES>>>(agg_a, D, x_a, D, wt_hi[1], wt_lo[1], b1_ha, h_a, D, NA, 1);

    // ---- Layer 2 ----
    agg_mean_kernel<<<divup(NH * 32, TB), TB>>>(h_a, ptr_h, csr_ah, agg_h, NH);
    gemm_mma_kernel<<<divup(NH, 128), TB, GSM_BYTES>>>(agg_h, D, h_h, D, wt_hi[2], wt_lo[2], b2_ah, z_h, D, NH, 0);
    agg_mean_kernel<<<divup(NA * 32, TB), TB>>>(h_h, ptr_a, csr_ha, agg_a, NA);
    gemm_mma_kernel<<<divup(NA, 128), TB, GSM_BYTES>>>(agg_a, D, h_a, D, wt_hi[3], wt_lo[3], b2_ha, z_a, D, NA, 0);

    // ---- Decoder ----
    gather_z1_kernel<<<divup(EL * 32, TB), TB>>>(z_a, z_h, e_row, e_col, z1, EL);
    gemm_mma_kernel<<<divup(EL, 128), TB, GSM_BYTES>>>(z1, 256, z1 + 128, 256, wt_hi[4], wt_lo[4], b_lin1, z2, D, EL, 1);
    pred_kernel<<<divup(EL * 32, TB), TB>>>(z2, W_lin2, b_lin2, pred, EL);
}

// round 16
// speedup vs baseline: 1.9511x; 1.0754x over previous
#include <cuda_runtime.h>
#include <cstdint>

#define NA 100000
#define NH 20000
#define NE 1000000
#define EL 200000
#define D  128

// ---------------- device scratch (static, no allocations) ----------------
__device__ int   g_cnt_a[NA];
__device__ int   g_cnt_h[NH];
__device__ int   g_ptr_a[NA + 1];
__device__ int   g_ptr_h[NH + 1];
__device__ int   g_cur_a[NA];
__device__ int   g_cur_h[NH];
__device__ int   g_csr_ah[NE];
__device__ int   g_csr_ha[NE];
__device__ float g_agg_a[(size_t)NA * D];
__device__ float g_agg_h[(size_t)NH * D];
__device__ float g_h_a[(size_t)NA * D];
__device__ float g_h_h[(size_t)NH * D];
__device__ float g_z_a[(size_t)NA * D];
__device__ float g_z_h[(size_t)NH * D];
// transposed + bf16 hi/lo split weights: 5 configs x {hi,lo} x [128 n][256 k] bf16
__device__ uint16_t g_wt[5][2][128 * 256];

// ---------------- PTX helpers (sm_80-compatible only; NO tcgen05) ----------------
__device__ __forceinline__ uint32_t smem_u32(const void* p) {
    uint32_t a;
    asm("{ .reg .u64 t; cvta.to.shared.u64 t, %1; cvt.u32.u64 %0, t; }" : "=r"(a) : "l"(p));
    return a;
}
// pack two fp32 into bf16x2: element0 (low 16 bits) = lo_elem, element1 = hi_elem
__device__ __forceinline__ uint32_t pack_bf16x2(float hi_elem, float lo_elem) {
    uint32_t d;
    asm("cvt.rn.bf16x2.f32 %0, %1, %2;" : "=r"(d) : "f"(hi_elem), "f"(lo_elem));
    return d;
}
__device__ __forceinline__ float bf16_lo_as_f32(uint32_t p) { return __uint_as_float(p << 16); }
__device__ __forceinline__ float bf16_hi_as_f32(uint32_t p) { return __uint_as_float(p & 0xFFFF0000u); }

#define LDSM_X4(r, addr) \
    asm volatile("ldmatrix.sync.aligned.m8n8.x4.shared.b16 {%0,%1,%2,%3}, [%4];" \
        : "=r"((r)[0]), "=r"((r)[1]), "=r"((r)[2]), "=r"((r)[3]) : "r"(addr))

__device__ __forceinline__ void mma_bf16(float* c, const uint32_t* a, const uint32_t* b) {
    asm volatile(
        "mma.sync.aligned.m16n8k16.row.col.f32.bf16.bf16.f32 "
        "{%0,%1,%2,%3}, {%4,%5,%6,%7}, {%8,%9}, {%0,%1,%2,%3};"
        : "+f"(c[0]), "+f"(c[1]), "+f"(c[2]), "+f"(c[3])
        : "r"(a[0]), "r"(a[1]), "r"(a[2]), "r"(a[3]), "r"(b[0]), "r"(b[1]));
}

// ---------------- small utility kernels ----------------
__global__ void zero_int_kernel(int* p, int n) {
    int i = blockIdx.x * blockDim.x + threadIdx.x;
    if (i < n) p[i] = 0;
}
__global__ void hist_kernel(const int* __restrict__ dst, int* __restrict__ cnt, int n) {
    int i = blockIdx.x * blockDim.x + threadIdx.x;
    if (i < n) atomicAdd(&cnt[dst[i]], 1);
}
__global__ void scatter_kernel(const int* __restrict__ src, const int* __restrict__ dst,
                               int* __restrict__ cur, int* __restrict__ csr, int n) {
    int i = blockIdx.x * blockDim.x + threadIdx.x;
    if (i < n) {
        int d = dst[i];
        int p = atomicAdd(&cur[d], 1);
        csr[p] = src[i];
    }
}
// single-block exclusive scan; writes ptr[0..n] AND cur[0..n-1] (= ptr value)
__global__ void exscan_kernel(const int* __restrict__ cnt, int* __restrict__ ptr,
                              int* __restrict__ cur, int n) {
    __shared__ int warp_sums[32];
    __shared__ int s_carry;
    int tid = threadIdx.x;
    int lane = tid & 31, wid = tid >> 5;
    if (tid == 0) s_carry = 0;
    __syncthreads();
    for (int base = 0; base < n; base += 1024) {
        int i = base + tid;
        int v = (i < n) ? cnt[i] : 0;
        int x = v;
        #pragma unroll
        for (int o = 1; o < 32; o <<= 1) {
            int y = __shfl_up_sync(0xFFFFFFFFu, x, o);
            if (lane >= o) x += y;
        }
        if (lane == 31) warp_sums[wid] = x;
        __syncthreads();
        if (wid == 0) {
            int s = warp_sums[lane];
            #pragma unroll
            for (int o = 1; o < 32; o <<= 1) {
                int y = __shfl_up_sync(0xFFFFFFFFu, s, o);
                if (lane >= o) s += y;
            }
            warp_sums[lane] = s;
        }
        __syncthreads();
        int incl = x + ((wid > 0) ? warp_sums[wid - 1] : 0);
        int carry = s_carry;
        if (i < n) { int e = carry + incl - v; ptr[i] = e; cur[i] = e; }
        __syncthreads();
        if (tid == 1023) s_carry = carry + incl;
        __syncthreads();
    }
    if (tid == 0) ptr[n] = s_carry;
}

// ---------------- mean aggregation: one warp per destination node ----------------
__global__ void agg_mean_kernel(const float* __restrict__ X,
                                const int* __restrict__ ptr,
                                const int* __restrict__ idx,
                                float* __restrict__ out, int n) {
    int w = (blockIdx.x * blockDim.x + threadIdx.x) >> 5;
    int lane = threadIdx.x & 31;
    if (w >= n) return;
    int s = ptr[w], e = ptr[w + 1];
    float ax = 0.f, ay = 0.f, az = 0.f, aw = 0.f;
    float bx = 0.f, by = 0.f, bz = 0.f, bw = 0.f;
    int i = s;
    for (; i + 4 <= e; i += 4) {
        int s0 = __ldg(&idx[i]);
        int s1 = __ldg(&idx[i + 1]);
        int s2 = __ldg(&idx[i + 2]);
        int s3 = __ldg(&idx[i + 3]);
        float4 v0 = *reinterpret_cast<const float4*>(X + (size_t)s0 * D + lane * 4);
        float4 v1 = *reinterpret_cast<const float4*>(X + (size_t)s1 * D + lane * 4);
        float4 v2 = *reinterpret_cast<const float4*>(X + (size_t)s2 * D + lane * 4);
        float4 v3 = *reinterpret_cast<const float4*>(X + (size_t)s3 * D + lane * 4);
        ax += v0.x; ay += v0.y; az += v0.z; aw += v0.w;
        bx += v1.x; by += v1.y; bz += v1.z; bw += v1.w;
        ax += v2.x; ay += v2.y; az += v2.z; aw += v2.w;
        bx += v3.x; by += v3.y; bz += v3.z; bw += v3.w;
    }
    for (; i < e; i++) {
        int s0 = __ldg(&idx[i]);
        float4 v0 = *reinterpret_cast<const float4*>(X + (size_t)s0 * D + lane * 4);
        ax += v0.x; ay += v0.y; az += v0.z; aw += v0.w;
    }
    ax += bx; ay += by; az += bz; aw += bw;
    int deg = e - s;
    float inv = 1.0f / (float)(deg > 0 ? deg : 1);
    float4 r = make_float4(ax * inv, ay * inv, az * inv, aw * inv);
    *reinterpret_cast<float4*>(out + (size_t)w * D + lane * 4) = r;
}

// ---------------- weight transpose + bf16 hi/lo split (all 5 configs, 1 launch) ----------------
struct WSplitArgs {
    const float* wl[5];
    const float* wr[5];
    uint16_t* hi[5];
    uint16_t* lo[5];
};
__global__ void wsplit_all_kernel(WSplitArgs a) {
    int cfg = blockIdx.y;
    int idx = blockIdx.x * blockDim.x + threadIdx.x;
    if (idx >= 128 * 256) return;
    int n = idx >> 8;
    int k = idx & 255;
    float v = (k < 128) ? a.wl[cfg][(size_t)k * 128 + n] : a.wr[cfg][(size_t)(k - 128) * 128 + n];
    uint32_t h = pack_bf16x2(0.f, v);           // low half = bf16(v)
    float hf = bf16_lo_as_f32(h);
    uint32_t l = pack_bf16x2(0.f, v - hf);
    a.hi[cfg][idx] = (uint16_t)(h & 0xFFFF);
    a.lo[cfg][idx] = (uint16_t)(l & 0xFFFF);
}

// ---------------- bf16-split tensor-core GEMM (mma.sync) ----------------
// C[M,128] = [A0 | A1] (K=256) @ Wt^T + bias, optional relu.
// Wt hi/lo: [128 n][256 k] bf16, pre-transposed & split.
// CTA tile 128x128, 8 warps in 2(M)x4(N), warp tile 64x32, K chunk = 32.
// SMEM row stride 80B (16B aligned; ldmatrix bank-conflict-free: 20i mod 32 distinct).
// A tiles: fp32->bf16 split via register staging. B tiles: cp.async (pre-split).
#define TSTRIDE 80
#define TILE_BYTES (128 * TSTRIDE)          // 10240
#define STAGE_BYTES (4 * TILE_BYTES)        // A_hi A_lo B_hi B_lo = 40960
#define GSM_BYTES (2 * STAGE_BYTES + 128)

__global__ void __launch_bounds__(256, 2)
gemm_mma_kernel(const float* __restrict__ A0, int lda0,
                const float* __restrict__ A1, int lda1,
                const uint16_t* __restrict__ Whi, const uint16_t* __restrict__ Wlo,
                const float* __restrict__ bias,
                float* __restrict__ C, int ldc, int M, int relu) {
    extern __shared__ char smem[];
    uint32_t tb = (smem_u32(smem) + 127) & ~127u;

    int tid = threadIdx.x;
    int wid = tid >> 5, lane = tid & 31;
    int warpM = wid >> 2;        // 0..1
    int warpN = wid & 3;         // 0..3
    int row0 = blockIdx.x * 128;

    float acc[4][4][4];
    #pragma unroll
    for (int mt = 0; mt < 4; mt++)
        #pragma unroll
        for (int nt = 0; nt < 4; nt++)
            #pragma unroll
            for (int j = 0; j < 4; j++) acc[mt][nt][j] = 0.f;

    float4 sA[4];   // register staging for next A chunk

    // ---- load A chunk kc into regs ----
    #define LD_A(kc)                                                                \
    do {                                                                            \
        const float* Ap = ((kc) < 4) ? A0 : A1;                                     \
        int lda = ((kc) < 4) ? lda0 : lda1;                                         \
        int koff = ((kc) & 3) * 32;                                                 \
        _Pragma("unroll")                                                           \
        for (int i = 0; i < 4; i++) {                                               \
            int p = tid + i * 256;                                                  \
            int r = p >> 3, c = p & 7;                                              \
            int gr = row0 + r;                                                      \
            sA[i] = (gr < M)                                                        \
                ? *reinterpret_cast<const float4*>(Ap + (size_t)gr * lda + koff + c * 4) \
                : make_float4(0.f, 0.f, 0.f, 0.f);                                  \
        }                                                                           \
    } while (0)

    // ---- split + store staged A regs into smem stage s ----
    #define ST_A(s)                                                                 \
    do {                                                                            \
        uint32_t base = tb + (s) * STAGE_BYTES;                                     \
        _Pragma("unroll")                                                           \
        for (int i = 0; i < 4; i++) {                                               \
            int p = tid + i * 256;                                                  \
            int r = p >> 3, c = p & 7;                                              \
            uint32_t h01 = pack_bf16x2(sA[i].y, sA[i].x);                           \
            uint32_t h23 = pack_bf16x2(sA[i].w, sA[i].z);                           \
            float lx = sA[i].x - bf16_lo_as_f32(h01);                               \
            float ly = sA[i].y - bf16_hi_as_f32(h01);                               \
            float lz = sA[i].z - bf16_lo_as_f32(h23);                               \
            float lw = sA[i].w - bf16_hi_as_f32(h23);                               \
            uint32_t l01 = pack_bf16x2(ly, lx);                                     \
            uint32_t l23 = pack_bf16x2(lw, lz);                                     \
            uint32_t ad = base + r * TSTRIDE + c * 8;                               \
            asm volatile("st.shared.v2.b32 [%0], {%1, %2};" :: "r"(ad), "r"(h01), "r"(h23) : "memory"); \
            asm volatile("st.shared.v2.b32 [%0], {%1, %2};" :: "r"(ad + TILE_BYTES), "r"(l01), "r"(l23) : "memory"); \
        }                                                                           \
    } while (0)

    // ---- async-copy B chunk kc into smem stage s (pre-split bf16, no conversion) ----
    #define CP_B(kc, s)                                                             \
    do {                                                                            \
        uint32_t bb = tb + (s) * STAGE_BYTES + 2 * TILE_BYTES;                      \
        _Pragma("unroll")                                                           \
        for (int i = 0; i < 2; i++) {                                               \
            int p = tid + i * 256;                                                  \
            int r = p >> 2, q = p & 3;                                              \
            size_t g = (size_t)r * 256 + (kc) * 32 + q * 8;                         \
            uint32_t dsm = bb + r * TSTRIDE + q * 16;                               \
            asm volatile("cp.async.cg.shared.global [%0], [%1], 16;"                \
                :: "r"(dsm), "l"(Whi + g) : "memory");                              \
            asm volatile("cp.async.cg.shared.global [%0], [%1], 16;"                \
                :: "r"(dsm + TILE_BYTES), "l"(Wlo + g) : "memory");                 \
        }                                                                           \
        asm volatile("cp.async.commit_group;" ::: "memory");                        \
    } while (0)

    // prologue: fill stage 0
    LD_A(0);
    CP_B(0, 0);
    ST_A(0);
    asm volatile("cp.async.wait_group 0;" ::: "memory");
    __syncthreads();

    #pragma unroll 1
    for (int kc = 0; kc < 8; ++kc) {
        int s = kc & 1;
        if (kc < 7) {
            LD_A(kc + 1);
            CP_B(kc + 1, s ^ 1);
        }

        // ---- compute on stage s ----
        {
            uint32_t base = tb + s * STAGE_BYTES;
            uint32_t aBase = base;
            uint32_t bBase = base + 2 * TILE_BYTES;
            #pragma unroll
            for (int ks = 0; ks < 2; ks++) {
                // B fragments: hi and lo
                uint32_t Bh[4][2], Bl[4][2];
                #pragma unroll
                for (int ng = 0; ng < 2; ng++) {
                    uint32_t ad = bBase + (warpN * 32 + ng * 16 + (lane & 15)) * TSTRIDE
                                + ks * 32 + (lane >> 4) * 16;
                    uint32_t r[4];
                    LDSM_X4(r, ad);
                    Bh[ng * 2][0] = r[0]; Bh[ng * 2][1] = r[2];
                    Bh[ng * 2 + 1][0] = r[1]; Bh[ng * 2 + 1][1] = r[3];
                    LDSM_X4(r, ad + TILE_BYTES);
                    Bl[ng * 2][0] = r[0]; Bl[ng * 2][1] = r[2];
                    Bl[ng * 2 + 1][0] = r[1]; Bl[ng * 2 + 1][1] = r[3];
                }
                #pragma unroll
                for (int mt = 0; mt < 4; mt++) {
                    uint32_t ad = aBase + (warpM * 64 + mt * 16 + (lane & 15)) * TSTRIDE
                                + ks * 32 + (lane >> 4) * 16;
                    uint32_t Ah[4];
                    LDSM_X4(Ah, ad);
                    #pragma unroll
                    for (int nt = 0; nt < 4; nt++) mma_bf16(acc[mt][nt], Ah, Bh[nt]); // hi*hi
                    #pragma unroll
                    for (int nt = 0; nt < 4; nt++) mma_bf16(acc[mt][nt], Ah, Bl[nt]); // hi*lo
                    uint32_t Al[4];
                    LDSM_X4(Al, ad + TILE_BYTES);
                    #pragma unroll
                    for (int nt = 0; nt < 4; nt++) mma_bf16(acc[mt][nt], Al, Bh[nt]); // lo*hi
                }
            }
        }

        __syncthreads();
        if (kc < 7) {
            ST_A(s ^ 1);
            asm volatile("cp.async.wait_group 0;" ::: "memory");
            __syncthreads();
        }
    }

    // ---- epilogue ----
    #pragma unroll
    for (int mt = 0; mt < 4; mt++) {
        int rg = row0 + warpM * 64 + mt * 16 + (lane >> 2);
        #pragma unroll
        for (int nt = 0; nt < 4; nt++) {
            int col = warpN * 32 + nt * 8 + ((lane & 3) << 1);
            float2 bv = *reinterpret_cast<const float2*>(bias + col);
            float2 o0, o1;
            o0.x = acc[mt][nt][0] + bv.x; o0.y = acc[mt][nt][1] + bv.y;
            o1.x = acc[mt][nt][2] + bv.x; o1.y = acc[mt][nt][3] + bv.y;
            if (relu) {
                o0.x = fmaxf(o0.x, 0.f); o0.y = fmaxf(o0.y, 0.f);
                o1.x = fmaxf(o1.x, 0.f); o1.y = fmaxf(o1.y, 0.f);
            }
            if (rg < M)     *reinterpret_cast<float2*>(C + (size_t)rg * ldc + col) = o0;
            if (rg + 8 < M) *reinterpret_cast<float2*>(C + (size_t)(rg + 8) * ldc + col) = o1;
        }
    }
    #undef LD_A
    #undef ST_A
    #undef CP_B
}

// ---------------- decoder: gather z1 rows (one warp per link edge) ----------------
__global__ void gather_z1_kernel(const float* __restrict__ za, const float* __restrict__ zh,
                                 const int* __restrict__ row, const int* __restrict__ col,
                                 float* __restrict__ z1, int n) {
    int w = (blockIdx.x * blockDim.x + threadIdx.x) >> 5;
    int lane = threadIdx.x & 31;
    if (w >= n) return;
    int r = __ldg(&row[w]);
    int c = __ldg(&col[w]);
    float4 a = *reinterpret_cast<const float4*>(za + (size_t)r * D + lane * 4);
    float4 b = *reinterpret_cast<const float4*>(zh + (size_t)c * D + lane * 4);
    *reinterpret_cast<float4*>(z1 + (size_t)w * 256 + lane * 4)       = a;
    *reinterpret_cast<float4*>(z1 + (size_t)w * 256 + 128 + lane * 4) = b;
}

// ---------------- pred = z2 @ W_lin2 + b_lin2 (one warp per row) ----------------
__global__ void pred_kernel(const float* __restrict__ z2, const float* __restrict__ w2,
                            const float* __restrict__ b2, float* __restrict__ out, int n) {
    int w = (blockIdx.x * blockDim.x + threadIdx.x) >> 5;
    int lane = threadIdx.x & 31;
    if (w >= n) return;
    float4 v  = *reinterpret_cast<const float4*>(z2 + (size_t)w * D + lane * 4);
    float4 ww = *reinterpret_cast<const float4*>(w2 + lane * 4);
    float s = v.x * ww.x + v.y * ww.y + v.z * ww.z + v.w * ww.w;
    #pragma unroll
    for (int o = 16; o > 0; o >>= 1) s += __shfl_xor_sync(0xFFFFFFFFu, s, o);
    if (lane == 0) out[w] = s + b2[0];
}

// ---------------- host launch ----------------
static inline int divup(int a, int b) { return (a + b - 1) / b; }

extern "C" void kernel_launch(void* const* d_in, const int* in_sizes, int n_in,
                              void* d_out, int out_size) {
    const float* x_a    = (const float*)d_in[0];
    const float* x_h    = (const float*)d_in[1];
    const int*   ah_src = (const int*)d_in[2];
    const int*   ah_dst = (const int*)d_in[3];
    const int*   ha_src = (const int*)d_in[4];
    const int*   ha_dst = (const int*)d_in[5];
    const int*   e_row  = (const int*)d_in[6];
    const int*   e_col  = (const int*)d_in[7];

    bool sig = (in_sizes[9] == 128);
    const float *W1_ah_l, *W1_ah_r, *W1_ha_l, *W1_ha_r;
    const float *W2_ah_l, *W2_ah_r, *W2_ha_l, *W2_ha_r;
    const float *b1_ah, *b1_ha, *b2_ah, *b2_ha;
    if (sig) {
        W1_ah_l = (const float*)d_in[8];  b1_ah = (const float*)d_in[9];
        W1_ah_r = (const float*)d_in[10];
        W1_ha_l = (const float*)d_in[11]; b1_ha = (const float*)d_in[12];
        W1_ha_r = (const float*)d_in[13];
        W2_ah_l = (const float*)d_in[14]; b2_ah = (const float*)d_in[15];
        W2_ah_r = (const float*)d_in[16];
        W2_ha_l = (const float*)d_in[17]; b2_ha = (const float*)d_in[18];
        W2_ha_r = (const float*)d_in[19];
    } else {
        W1_ah_l = (const float*)d_in[8];  W1_ah_r = (const float*)d_in[9];
        W1_ha_l = (const float*)d_in[10]; W1_ha_r = (const float*)d_in[11];
        W2_ah_l = (const float*)d_in[12]; W2_ah_r = (const float*)d_in[13];
        W2_ha_l = (const float*)d_in[14]; W2_ha_r = (const float*)d_in[15];
        b1_ah = (const float*)d_in[16];   b1_ha = (const float*)d_in[17];
        b2_ah = (const float*)d_in[18];   b2_ha = (const float*)d_in[19];
    }
    const float* W_lin1 = (const float*)d_in[20];
    const float* b_lin1 = (const float*)d_in[21];
    const float* W_lin2 = (const float*)d_in[22];
    const float* b_lin2 = (const float*)d_in[23];

    float* out  = (float*)d_out;
    float* pred = out;
    float* z1   = out + EL;
    float* z2   = out + EL + (size_t)EL * 256;

    int *cnt_a, *cnt_h, *ptr_a, *ptr_h, *cur_a, *cur_h, *csr_ah, *csr_ha;
    float *agg_a, *agg_h, *h_a, *h_h, *z_a, *z_h;
    uint16_t* wt;
    cudaGetSymbolAddress((void**)&cnt_a, g_cnt_a);
    cudaGetSymbolAddress((void**)&cnt_h, g_cnt_h);
    cudaGetSymbolAddress((void**)&ptr_a, g_ptr_a);
    cudaGetSymbolAddress((void**)&ptr_h, g_ptr_h);
    cudaGetSymbolAddress((void**)&cur_a, g_cur_a);
    cudaGetSymbolAddress((void**)&cur_h, g_cur_h);
    cudaGetSymbolAddress((void**)&csr_ah, g_csr_ah);
    cudaGetSymbolAddress((void**)&csr_ha, g_csr_ha);
    cudaGetSymbolAddress((void**)&agg_a, g_agg_a);
    cudaGetSymbolAddress((void**)&agg_h, g_agg_h);
    cudaGetSymbolAddress((void**)&h_a, g_h_a);
    cudaGetSymbolAddress((void**)&h_h, g_h_h);
    cudaGetSymbolAddress((void**)&z_a, g_z_a);
    cudaGetSymbolAddress((void**)&z_h, g_z_h);
    cudaGetSymbolAddress((void**)&wt, g_wt);

    const int WSZ = 128 * 256;
    uint16_t* wt_hi[5]; uint16_t* wt_lo[5];
    for (int i = 0; i < 5; i++) { wt_hi[i] = wt + (size_t)i * 2 * WSZ; wt_lo[i] = wt_hi[i] + WSZ; }

    cudaFuncSetAttribute(gemm_mma_kernel, cudaFuncAttributeMaxDynamicSharedMemorySize, GSM_BYTES);

    const int TB = 256;

    // ---- weight transpose + split (single launch, all 5 configs) ----
    WSplitArgs wa;
    wa.wl[0] = W1_ah_l; wa.wr[0] = W1_ah_r;
    wa.wl[1] = W1_ha_l; wa.wr[1] = W1_ha_r;
    wa.wl[2] = W2_ah_l; wa.wr[2] = W2_ah_r;
    wa.wl[3] = W2_ha_l; wa.wr[3] = W2_ha_r;
    wa.wl[4] = W_lin1;  wa.wr[4] = W_lin1 + 128 * 128;
    for (int i = 0; i < 5; i++) { wa.hi[i] = wt_hi[i]; wa.lo[i] = wt_lo[i]; }
    {
        dim3 grid(divup(WSZ, TB), 5);
        wsplit_all_kernel<<<grid, TB>>>(wa);
    }

    // ---- CSR build: a->h edges grouped by hotel dst ----
    zero_int_kernel<<<divup(NH, TB), TB>>>(cnt_h, NH);
    hist_kernel<<<divup(NE, TB), TB>>>(ah_dst, cnt_h, NE);
    exscan_kernel<<<1, 1024>>>(cnt_h, ptr_h, cur_h, NH);
    scatter_kernel<<<divup(NE, TB), TB>>>(ah_src, ah_dst, cur_h, csr_ah, NE);

    // ---- CSR build: h->a edges grouped by author dst ----
    zero_int_kernel<<<divup(NA, TB), TB>>>(cnt_a, NA);
    hist_kernel<<<divup(NE, TB), TB>>>(ha_dst, cnt_a, NE);
    exscan_kernel<<<1, 1024>>>(cnt_a, ptr_a, cur_a, NA);
    scatter_kernel<<<divup(NE, TB), TB>>>(ha_src, ha_dst, cur_a, csr_ha, NE);

    // ---- Layer 1 ----
    agg_mean_kernel<<<divup(NH * 32, TB), TB>>>(x_a, ptr_h, csr_ah, agg_h, NH);
    gemm_mma_kernel<<<divup(NH, 128), TB, GSM_BYTES>>>(agg_h, D, x_h, D, wt_hi[0], wt_lo[0], b1_ah, h_h, D, NH, 1);
    agg_mean_kernel<<<divup(NA * 32, TB), TB>>>(x_h, ptr_a, csr_ha, agg_a, NA);
    gemm_mma_kernel<<<divup(NA, 128), TB, GSM_BYTES>>>(agg_a, D, x_a, D, wt_hi[1], wt_lo[1], b1_ha, h_a, D, NA, 1);

    // ---- Layer 2 ----
    agg_mean_kernel<<<divup(NH * 32, TB), TB>>>(h_a, ptr_h, csr_ah, agg_h, NH);
    gemm_mma_kernel<<<divup(NH, 128), TB, GSM_BYTES>>>(agg_h, D, h_h, D, wt_hi[2], wt_lo[2], b2_ah, z_h, D, NH, 0);
    agg_mean_kernel<<<divup(NA * 32, TB), TB>>>(h_h, ptr_a, csr_ha, agg_a, NA);
    gemm_mma_kernel<<<divup(NA, 128), TB, GSM_BYTES>>>(agg_a, D, h_a, D, wt_hi[3], wt_lo[3], b2_ha, z_a, D, NA, 0);

    // ---- Decoder ----
    gather_z1_kernel<<<divup(EL * 32, TB), TB>>>(z_a, z_h, e_row, e_col, z1, EL);
    gemm_mma_kernel<<<divup(EL, 128), TB, GSM_BYTES>>>(z1, 256, z1 + 128, 256, wt_hi[4], wt_lo[4], b_lin1, z2, D, EL, 1);
    pred_kernel<<<divup(EL * 32, TB), TB>>>(z2, W_lin2, b_lin2, pred, EL);
}